// round 9
// baseline (speedup 1.0000x reference)
#include <cuda_runtime.h>
#include <cuda_bf16.h>
#include <cuda_pipeline.h>
#include <cstdint>

#define BATCHN 4096
#define NCC    32
#define NTT    64
#define NP     (BATCHN*NCC)   // 131072

// ---------------- scratch (static device globals; no allocation) ----------------
__device__ float4 g_FRF[BATCHN*NTT];
__device__ float4 g_colsum[BATCHN];
__device__ float2 g_cross[BATCHN];
__device__ float4 g_Hc[NP*2];
__device__ float  g_xin[NP*8];
__device__ float  g_xout[NP*8];
__device__ float4 g_V[NP*2];
__device__ float  g_Pw[NP];
__device__ float  g_part15[256][16];
__device__ float  g_sum15[5][16];
__device__ int    g_dec5[5];
__device__ unsigned g_ticket;
// bf16 hi/lo split weights, chunk-major layout: [kchunk(16)][n(256)][kk(16)]
__device__ __nv_bfloat16 g_W1hi[65536], g_W1lo[65536], g_W2hi[65536], g_W2lo[65536];

// ---------------- complex helpers ----------------
struct cf { float r, i; };
__device__ __forceinline__ cf cmul(cf a, cf b){ return {a.r*b.r - a.i*b.i, a.r*b.i + a.i*b.r}; }
__device__ __forceinline__ cf cadd(cf a, cf b){ return {a.r+b.r, a.i+b.i}; }
__device__ __forceinline__ cf csub(cf a, cf b){ return {a.r-b.r, a.i-b.i}; }
__device__ __forceinline__ cf cconj(cf a){ return {a.r, -a.i}; }
__device__ __forceinline__ float cabs2(cf a){ return a.r*a.r + a.i*a.i; }

// ---------------- warp mma helpers (plain sm_100 PTX) ----------------
__device__ __forceinline__ uint32_t smem_u32(const void* p){
    uint32_t a;
    asm("{ .reg .u64 t; cvta.to.shared.u64 t, %1; cvt.u32.u64 %0, t; }" : "=r"(a) : "l"(p));
    return a;
}
__device__ __forceinline__ void ldsm4(uint32_t* r, uint32_t addr){
    asm volatile("ldmatrix.sync.aligned.m8n8.x4.shared.b16 {%0,%1,%2,%3},[%4];"
                 : "=r"(r[0]),"=r"(r[1]),"=r"(r[2]),"=r"(r[3]) : "r"(addr));
}
__device__ __forceinline__ void mma_bf16(float* c, const uint32_t* a, const uint32_t* b){
    asm volatile("mma.sync.aligned.m16n8k16.row.col.f32.bf16.bf16.f32 "
                 "{%0,%1,%2,%3},{%4,%5,%6,%7},{%8,%9},{%0,%1,%2,%3};"
                 : "+f"(c[0]),"+f"(c[1]),"+f"(c[2]),"+f"(c[3])
                 : "r"(a[0]),"r"(a[1]),"r"(a[2]),"r"(a[3]), "r"(b[0]),"r"(b[1]));
}
__device__ __forceinline__ uint32_t pack_bf16x2(float even, float odd){
    uint32_t r;
    asm("cvt.rn.bf16x2.f32 %0, %1, %2;" : "=r"(r) : "f"(odd), "f"(even));  // low=even, high=odd
    return r;
}

// ---------------- K1: F_RF + column sums + cross ----------------
__global__ void k1_frf(const float* __restrict__ H){
    int b = blockIdx.x;
    int t = threadIdx.x;     // 64 threads
    const float* r0 = H + ((size_t)(b*2+0)*32 + 16)*128;
    const float* r1 = H + ((size_t)(b*2+1)*32 + 16)*128;
    float h0a = r0[0], h0b = r1[0];
    float hra = r0[t], hrb = r1[t];
    float inva = 1.0f/(8.0f*sqrtf(hra*hra + h0a*h0a));
    float invb = 1.0f/(8.0f*sqrtf(hrb*hrb + h0b*h0b));
    float f0r =  hra*inva, f0i = -h0a*inva;
    float f1r =  hrb*invb, f1i = -h0b*invb;
    g_FRF[b*64+t] = make_float4(f0r, f0i, f1r, f1i);
    float cr = f0r*f1r + f0i*f1i;
    float ci = f0i*f1r - f0r*f1i;
    __shared__ float s[6*64];
    s[0*64+t]=f0r; s[1*64+t]=f0i; s[2*64+t]=f1r; s[3*64+t]=f1i; s[4*64+t]=cr; s[5*64+t]=ci;
    __syncthreads();
    for (int off=32; off>=1; off>>=1){
        if (t < off){
            #pragma unroll
            for (int i=0;i<6;i++) s[i*64+t] += s[i*64+t+off];
        }
        __syncthreads();
    }
    if (t==0){
        g_colsum[b] = make_float4(s[0], s[64], s[128], s[192]);
        g_cross[b]  = make_float2(s[256], s[320]);
    }
}

// ---------------- K2: H_equ (normalized) + MLP input ----------------
__global__ void k2_hequ(const float* __restrict__ H){
    __shared__ float4 sfrf[64];
    __shared__ float4 scs;
    int b2 = blockIdx.x >> 2;
    int g  = blockIdx.x & 3;
    int tid = threadIdx.x;
    if (tid < 64) sfrf[tid] = g_FRF[b2*64 + tid];
    if (tid == 64) scs = g_colsum[b2];
    __syncthreads();
    int w = tid >> 5, l = tid & 31;
    int p = (g*8 + w)*4096 + b2;
    const float* r0 = H + (size_t)(2*p)*128;
    const float* r1 = r0 + 128;
    float h00 = r0[0], h01 = r1[0];
    float a00r=0,a00i=0,a01r=0,a01i=0,a10r=0,a10i=0,a11r=0,a11i=0;
    #pragma unroll
    for (int k=0;k<2;k++){
        int tt = l + k*32;
        float4 f = sfrf[tt];
        float x0 = r0[tt], x1 = r1[tt];
        a00r += x0*f.x; a00i += x0*f.y; a01r += x0*f.z; a01i += x0*f.w;
        a10r += x1*f.x; a10i += x1*f.y; a11r += x1*f.z; a11i += x1*f.w;
    }
    #pragma unroll
    for (int off=16; off; off>>=1){
        a00r += __shfl_down_sync(0xffffffffu, a00r, off);
        a00i += __shfl_down_sync(0xffffffffu, a00i, off);
        a01r += __shfl_down_sync(0xffffffffu, a01r, off);
        a01i += __shfl_down_sync(0xffffffffu, a01i, off);
        a10r += __shfl_down_sync(0xffffffffu, a10r, off);
        a10i += __shfl_down_sync(0xffffffffu, a10i, off);
        a11r += __shfl_down_sync(0xffffffffu, a11r, off);
        a11i += __shfl_down_sync(0xffffffffu, a11i, off);
    }
    if (l == 0){
        float4 cs = scs;
        float m00r = a00r - h00*cs.y, m00i = a00i + h00*cs.x;
        float m01r = a01r - h00*cs.w, m01i = a01i + h00*cs.z;
        float m10r = a10r - h01*cs.y, m10i = a10i + h01*cs.x;
        float m11r = a11r - h01*cs.w, m11i = a11i + h01*cs.z;
        float pw = m00r*m00r+m00i*m00i+m01r*m01r+m01i*m01i
                 + m10r*m10r+m10i*m10i+m11r*m11r+m11i*m11i;
        float inv = 1.0f/sqrtf(pw);
        m00r*=inv; m00i*=inv; m01r*=inv; m01i*=inv;
        m10r*=inv; m10i*=inv; m11r*=inv; m11i*=inv;
        g_Hc[2*p]   = make_float4(m00r,m00i,m01r,m01i);
        g_Hc[2*p+1] = make_float4(m10r,m10i,m11r,m11i);
        float* xo = g_xin + (size_t)p*8;
        xo[0]=m00r; xo[1]=m01r; xo[2]=m10r; xo[3]=m11r;
        xo[4]=m00i; xo[5]=m01i; xo[6]=m10i; xo[7]=m11i;
    }
}

// ---------------- weight split: W[k][n] -> chunk-major bf16 hi/lo ----------------
// pos = (k>>4)*4096 + n*16 + (k&15)
__global__ void k_wsplit(const float* __restrict__ W1, const float* __restrict__ W2){
    int idx = blockIdx.x*256 + threadIdx.x;     // 0..131071
    int layer = idx >> 16;
    int e = idx & 65535;
    int n = e & 255, k = e >> 8;
    float v = (layer ? W2 : W1)[k*256 + n];
    __nv_bfloat16 h = __float2bfloat16(v);
    __nv_bfloat16 l = __float2bfloat16(v - __bfloat162float(h));
    int pos = (k >> 4)*4096 + n*16 + (k & 15);
    if (layer){ g_W2hi[pos] = h; g_W2lo[pos] = l; }
    else      { g_W1hi[pos] = h; g_W1lo[pos] = l; }
}

// ---------------- K3: mma.sync bf16x3 fused MLP (512 threads, 16 warps) ----------------
#define SA_HI   0          // 128 rows x stride 528B = 67584
#define SA_LO   67584
#define SW_OFF  135168     // 2 buf x (hi 12288 + lo 12288) = 49152
#define SW0_OFF 184320
#define SW3_OFF 192512
#define SB0_OFF 200704
#define SB1_OFF 201728
#define SB2_OFF 202752
#define SB3_OFF 203776
#define K3_SMEM 203904

__device__ __forceinline__ void issue_w(char* sm, int layer, int c, int buf, int tid){
    const __nv_bfloat16* gh = layer ? g_W2hi : g_W1hi;
    const __nv_bfloat16* gl = layer ? g_W2lo : g_W1lo;
    char* dhi = sm + SW_OFF + buf*24576;
    char* dlo = dhi + 12288;
    int n = tid >> 1, h8 = tid & 1;
    __pipeline_memcpy_async(dhi + n*48 + h8*16, gh + c*4096 + n*16 + h8*8, 16);
    __pipeline_memcpy_async(dlo + n*48 + h8*16, gl + c*4096 + n*16 + h8*8, 16);
    __pipeline_commit();
}

__global__ void __launch_bounds__(512, 1) k3_mma(
        const float* __restrict__ W0, const float* __restrict__ b0v,
        const float* __restrict__ b1v, const float* __restrict__ b2v,
        const float* __restrict__ W3, const float* __restrict__ b3v){
    extern __shared__ char sm[];
    uint32_t sbase = smem_u32(sm);
    int tid  = threadIdx.x;
    int wid  = tid >> 5, lane = tid & 31;
    int wm   = wid >> 3;        // rowgroup 0..1 (64 rows)
    int wn   = wid & 7;         // ngroup  0..7 (32 cols)

    issue_w(sm, 0, 0, 0, tid);
    issue_w(sm, 0, 1, 1, tid);

    float* sW0 = (float*)(sm + SW0_OFF);
    float* sW3 = (float*)(sm + SW3_OFF);
    float* sB0 = (float*)(sm + SB0_OFF);
    float* sB1 = (float*)(sm + SB1_OFF);
    float* sB2 = (float*)(sm + SB2_OFF);
    float* sB3 = (float*)(sm + SB3_OFF);
    #pragma unroll
    for (int i = tid; i < 2048; i += 512){ sW0[i] = W0[i]; sW3[i] = W3[i]; }
    if (tid < 256){ sB0[tid] = b0v[tid]; sB1[tid] = b1v[tid]; sB2[tid] = b2v[tid]; }
    if (tid >= 256 && tid < 264) sB3[tid-256] = b3v[tid-256];

    // ---- layer0: 8 -> 256 FFMA, split, write SA (4 threads per row) ----
    int r = tid >> 2, h = tid & 3;
    int grow = blockIdx.x*128 + r;
    float xr[8];
    {
        float4 a = *(const float4*)(g_xin + (size_t)grow*8);
        float4 b = *(const float4*)(g_xin + (size_t)grow*8 + 4);
        xr[0]=a.x; xr[1]=a.y; xr[2]=a.z; xr[3]=a.w;
        xr[4]=b.x; xr[5]=b.y; xr[6]=b.z; xr[7]=b.w;
    }
    __syncthreads();
    {
        char* rowh = sm + SA_HI + r*528;
        char* rowl = sm + SA_LO + r*528;
        #pragma unroll 4
        for (int cc = 0; cc < 32; cc++){
            int c0 = h*64 + 2*cc;
            float e = sB0[c0], o = sB0[c0+1];
            #pragma unroll
            for (int i = 0; i < 8; i++){
                e += xr[i]*sW0[i*256 + c0];
                o += xr[i]*sW0[i*256 + c0 + 1];
            }
            e = fmaxf(e, 0.f); o = fmaxf(o, 0.f);
            uint32_t hi = pack_bf16x2(e, o);
            float eh = __uint_as_float(hi << 16);
            float oh = __uint_as_float(hi & 0xffff0000u);
            uint32_t lo = pack_bf16x2(e - eh, o - oh);
            *(uint32_t*)(rowh + c0*2) = hi;
            *(uint32_t*)(rowl + c0*2) = lo;
        }
    }
    __syncthreads();

    // ---- layers 1,2: mma (each warp: 64 rows x 32 cols) ----
    float acc[64];
    #pragma unroll
    for (int i = 0; i < 64; i++) acc[i] = 0.f;

    int arow   = wm*64 + (lane & 15);
    uint32_t aoff = (uint32_t)arow*528 + ((lane >> 4) & 1)*16;
    int nrow   = wn*32 + (lane & 7) + ((lane & 16) >> 1);
    uint32_t boff = (uint32_t)nrow*48 + ((lane >> 3) & 1)*16;

    #pragma unroll 1
    for (int layer = 0; layer < 2; layer++){
        #pragma unroll 1
        for (int c = 0; c < 16; c++){
            if (c < 15) __pipeline_wait_prior(1);
            else        __pipeline_wait_prior(0);
            __syncthreads();
            int buf = c & 1;
            uint32_t wbh = sbase + SW_OFF + buf*24576 + boff;
            uint32_t wbl = wbh + 12288;
            uint32_t bh[8], bl[8];
            #pragma unroll
            for (int ntp = 0; ntp < 2; ntp++){
                ldsm4(&bh[ntp*4], wbh + ntp*768);
                ldsm4(&bl[ntp*4], wbl + ntp*768);
            }
            uint32_t abase = sbase + aoff + (uint32_t)c*32;
            #pragma unroll
            for (int prod = 0; prod < 3; prod++){
                const uint32_t bufsel = (prod == 1) ? (uint32_t)SA_LO : (uint32_t)SA_HI;
                const uint32_t* Bf = (prod == 2) ? bl : bh;
                #pragma unroll
                for (int mf = 0; mf < 4; mf++){
                    uint32_t av[4];
                    ldsm4(av, abase + bufsel + mf*8448);
                    #pragma unroll
                    for (int nt = 0; nt < 4; nt++){
                        mma_bf16(&acc[(mf*4 + nt)*4], av,
                                 &Bf[(nt >> 1)*4 + (nt & 1)*2]);
                    }
                }
            }
            __syncthreads();
            if (c + 2 < 16) issue_w(sm, layer, c + 2, c & 1, tid);
        }
        if (layer == 0){
            issue_w(sm, 1, 0, 0, tid);
            issue_w(sm, 1, 1, 1, tid);
        }
        // epilogue: bias + ReLU + split, write SA in place, reset acc
        const float* sb = layer ? sB2 : sB1;
        int erow = wm*64 + (lane >> 2);
        int ecol = wn*32 + (lane & 3)*2;
        #pragma unroll
        for (int mf = 0; mf < 4; mf++){
            #pragma unroll
            for (int nt = 0; nt < 4; nt++){
                float* C = &acc[(mf*4 + nt)*4];
                int col = ecol + nt*8;
                float bv0 = sb[col], bv1 = sb[col+1];
                #pragma unroll
                for (int half = 0; half < 2; half++){
                    int row = erow + mf*16 + half*8;
                    float v0 = fmaxf(C[half*2]   + bv0, 0.f);
                    float v1 = fmaxf(C[half*2+1] + bv1, 0.f);
                    uint32_t hi = pack_bf16x2(v0, v1);
                    float eh = __uint_as_float(hi << 16);
                    float oh = __uint_as_float(hi & 0xffff0000u);
                    uint32_t lo = pack_bf16x2(v0 - eh, v1 - oh);
                    *(uint32_t*)(sm + SA_HI + row*528 + col*2) = hi;
                    *(uint32_t*)(sm + SA_LO + row*528 + col*2) = lo;
                    C[half*2] = 0.f; C[half*2+1] = 0.f;
                }
            }
        }
        __syncthreads();
    }

    // ---- layer3: 256 -> 8 FFMA from SA (4 threads per row) ----
    {
        float a3[8];
        #pragma unroll
        for (int cc = 0; cc < 8; cc++) a3[cc] = 0.f;
        char* rowh = sm + SA_HI + r*528;
        char* rowl = sm + SA_LO + r*528;
        #pragma unroll 4
        for (int kk = 0; kk < 32; kk++){
            int k = h*64 + 2*kk;
            uint32_t wh = *(uint32_t*)(rowh + k*2);
            uint32_t wl = *(uint32_t*)(rowl + k*2);
            float v0 = __uint_as_float(wh << 16)          + __uint_as_float(wl << 16);
            float v1 = __uint_as_float(wh & 0xffff0000u)  + __uint_as_float(wl & 0xffff0000u);
            #pragma unroll
            for (int cc = 0; cc < 8; cc++){
                a3[cc] += v0*sW3[k*8 + cc] + v1*sW3[(k+1)*8 + cc];
            }
        }
        #pragma unroll
        for (int cc = 0; cc < 8; cc++){
            a3[cc] += __shfl_xor_sync(0xffffffffu, a3[cc], 1);
            a3[cc] += __shfl_xor_sync(0xffffffffu, a3[cc], 2);
        }
        if (h == 0){
            float* xo = g_xout + (size_t)grow*8;
            #pragma unroll
            for (int cc = 0; cc < 8; cc++) xo[cc] = a3[cc] + sB3[cc];
        }
    }
}

// ---------------- init ----------------
__global__ void k_init(){
    g_ticket = 0u;
    for (int i = 0; i < 5; i++) g_dec5[i] = 0;
}

// ---------------- K4 + bisection(4 steps/barrier) + K5 fused (R8-proven) ----------------
__global__ void __launch_bounds__(256, 2) k_bis(){
    int tid = threadIdx.x;
    int bid = blockIdx.x;
    int gid = bid*256 + tid;        // 0..65535
    int lane = tid & 31, wid = tid >> 5;

    float A0[2],A1[2],A2[2],Cc0[2],Cc1[2],Cc2[2],Cc3[2];
    float Bar[2],Bai[2],Bbr[2],Bbi[2],Bcr[2],Bci[2],Bdr[2],Bdi[2];
    float uwr0[2],uwi0[2],uwr1[2],uwi1[2];
    float hc[2][8];

    #pragma unroll
    for (int q = 0; q < 2; q++){
        int p = gid + q*65536;
        float4 hc0 = g_Hc[2*p], hc1 = g_Hc[2*p+1];
        hc[q][0]=hc0.x; hc[q][1]=hc0.y; hc[q][2]=hc0.z; hc[q][3]=hc0.w;
        hc[q][4]=hc1.x; hc[q][5]=hc1.y; hc[q][6]=hc1.z; hc[q][7]=hc1.w;
        const float* x = g_xout + (size_t)p*8;
        float x0=x[0],x1=x[1],x2=x[2],x3=x[3],x4=x[4],x5=x[5],x6=x[6],x7=x[7];
        cf U0{x0,x2}, U1{x1,x3}, Wm0{x4,x6}, Wm1{x5,x7};
        float au0 = x0*x0 + x2*x2, au1 = x1*x1 + x3*x3;
        cf c0{Wm0.r*au0, Wm0.i*au0}, c1{Wm1.r*au1, Wm1.i*au1};
        cf h00{hc0.x,hc0.y}, h01{hc0.z,hc0.w}, h10{hc1.x,hc1.y}, h11{hc1.z,hc1.w};
        float n00 = cabs2(h00), n01 = cabs2(h01), n10 = cabs2(h10), n11 = cabs2(h11);
        cf Ba{c0.r*n00 + c1.r*n10, c0.i*n00 + c1.i*n10};
        cf Bd{c0.r*n01 + c1.r*n11, c0.i*n01 + c1.i*n11};
        cf Bb = cadd(cmul(c0, cmul(cconj(h00), h01)), cmul(c1, cmul(cconj(h10), h11)));
        cf Bc = cadd(cmul(c0, cmul(cconj(h01), h00)), cmul(c1, cmul(cconj(h11), h10)));
        cf uw0 = cmul(U0, Wm0), uw1 = cmul(U1, Wm1);
        cf g00 = cconj(h00), g01 = cconj(h01), g10 = cconj(h10), g11 = cconj(h11);
        cf p00 = csub(cmul(Bd,g00), cmul(Bb,g01));
        cf p01 = csub(cmul(Ba,g01), cmul(Bc,g00));
        cf p10 = csub(cmul(Bd,g10), cmul(Bb,g11));
        cf p11 = csub(cmul(Ba,g11), cmul(Bc,g10));
        float u0 = cabs2(uw0), u1 = cabs2(uw1);
        A0[q] = u0*(cabs2(p00)+cabs2(p01)) + u1*(cabs2(p10)+cabs2(p11));
        A1[q] = 2.f*( u0*(p00.r*g00.r + p00.i*g00.i + p01.r*g01.r + p01.i*g01.i)
                    + u1*(p10.r*g10.r + p10.i*g10.i + p11.r*g11.r + p11.i*g11.i) );
        A2[q] = u0*(cabs2(g00)+cabs2(g01)) + u1*(cabs2(g10)+cabs2(g11));
        cf T = cadd(Ba, Bd);
        cf D = csub(cmul(Ba,Bd), cmul(Bb,Bc));
        Cc0[q] = cabs2(D);
        Cc1[q] = 2.f*(T.r*D.r + T.i*D.i);
        Cc2[q] = T.r*T.r + T.i*T.i + 2.f*D.r;
        Cc3[q] = 2.f*T.r;
        Bar[q]=Ba.r; Bai[q]=Ba.i; Bbr[q]=Bb.r; Bbi[q]=Bb.i;
        Bcr[q]=Bc.r; Bci[q]=Bc.i; Bdr[q]=Bd.r; Bdi[q]=Bd.i;
        uwr0[q]=uw0.r; uwi0[q]=uw0.i; uwr1[q]=uw1.r; uwi1[q]=uw1.i;
    }

    __shared__ float swarp[8][16];
    __shared__ float spart[16][16];
    __shared__ float ssum[16];
    __shared__ int   slast;
    float lo = 0.f, hi = 10.f, mu = 5.f;

    #pragma unroll 1
    for (int round = 0; round < 5; round++){
        float L[16], Hh[16], m[16];
        L[1] = lo; Hh[1] = hi;
        #pragma unroll
        for (int i = 1; i < 8; i++){
            m[i] = 0.5f*(L[i] + Hh[i]);
            L[2*i] = L[i];  Hh[2*i] = m[i];
            L[2*i+1] = m[i]; Hh[2*i+1] = Hh[i];
        }
        #pragma unroll
        for (int i = 8; i < 16; i++) m[i] = 0.5f*(L[i] + Hh[i]);

        float v[15];
        #pragma unroll
        for (int node = 1; node <= 15; node++){
            float s = 2.0f*m[node];
            float a = 0.f;
            #pragma unroll
            for (int q = 0; q < 2; q++){
                float num = A0[q] + s*(A1[q] + s*A2[q]);
                float den = Cc0[q] + s*(Cc1[q] + s*(Cc2[q] + s*(Cc3[q] + s)));
                a += num/den;
            }
            v[node-1] = a;
        }
        #pragma unroll
        for (int j = 0; j < 15; j++){
            #pragma unroll
            for (int off = 16; off; off >>= 1)
                v[j] += __shfl_down_sync(0xffffffffu, v[j], off);
            if (lane == 0) swarp[wid][j] = v[j];
        }
        __syncthreads();
        if (tid < 15){
            float s = 0.f;
            #pragma unroll
            for (int w = 0; w < 8; w++) s += swarp[w][tid];
            g_part15[bid][tid] = s;
        }
        __threadfence();
        __syncthreads();
        if (tid == 0){
            unsigned old = atomicAdd(&g_ticket, 1u);
            slast = (old == (unsigned)(256*(round+1) - 1)) ? 1 : 0;
        }
        __syncthreads();
        if (slast){
            int j = tid & 15, chunk = tid >> 4;
            float sacc = 0.f;
            if (j < 15){
                volatile float* gp = &g_part15[0][0];
                int base = chunk*16;
                #pragma unroll
                for (int i = 0; i < 16; i++) sacc += gp[(base + i)*16 + j];
            }
            spart[chunk][j] = sacc;
            __syncthreads();
            if (tid < 15){
                float s = 0.f;
                #pragma unroll
                for (int cc = 0; cc < 16; cc++) s += spart[cc][tid];
                g_sum15[round][tid] = s;
            }
            __threadfence();
            __syncthreads();
            if (tid == 0){ g_dec5[round] = 1; __threadfence(); }
        }
        if (tid == 0){
            volatile int* dp = (volatile int*)&g_dec5[round];
            int d;
            do { d = *dp; } while (d == 0);
            __threadfence();
            volatile float* gs = &g_sum15[round][0];
            #pragma unroll
            for (int j = 0; j < 15; j++) ssum[j] = gs[j];
        }
        __syncthreads();
        float Lc = lo, Hc = hi;
        int node = 1;
        #pragma unroll
        for (int st = 0; st < 4; st++){
            float mm = 0.5f*(Lc + Hc);
            float S = ssum[node-1];
            mu = mm;
            if (S > 1.0f){ Lc = mm; node = 2*node + 1; }
            else         { Hc = mm; node = 2*node; }
        }
        lo = Lc; hi = Hc;
        __syncthreads();
    }

    // epilogue: final V + per-item power
    float s = 2.0f*mu;
    #pragma unroll
    for (int q = 0; q < 2; q++){
        int p = gid + q*65536;
        cf a{Bar[q] + s, Bai[q]}, b{Bbr[q], Bbi[q]}, c{Bcr[q], Bci[q]}, d{Bdr[q] + s, Bdi[q]};
        cf det = csub(cmul(a,d), cmul(b,c));
        float id = 1.0f/cabs2(det);
        cf idet{det.r*id, -det.i*id};
        cf g00{hc[q][0],-hc[q][1]}, g01{hc[q][2],-hc[q][3]};
        cf g10{hc[q][4],-hc[q][5]}, g11{hc[q][6],-hc[q][7]};
        cf y00 = cmul(csub(cmul(d,g00), cmul(b,g01)), idet);
        cf y01 = cmul(csub(cmul(a,g01), cmul(c,g00)), idet);
        cf y10 = cmul(csub(cmul(d,g10), cmul(b,g11)), idet);
        cf y11 = cmul(csub(cmul(a,g11), cmul(c,g10)), idet);
        cf uw0{uwr0[q],uwi0[q]}, uw1{uwr1[q],uwi1[q]};
        cf V00 = cmul(uw0,y00);
        cf V01 = cmul(uw1,y10);
        cf V10 = cmul(uw0,y01);
        cf V11 = cmul(uw1,y11);
        g_V[2*p]   = make_float4(V00.r,V00.i,V01.r,V01.i);
        g_V[2*p+1] = make_float4(V10.r,V10.i,V11.r,V11.i);
        float2 cr = g_cross[p & 4095];
        cf crs{cr.x, cr.y};
        cf t0 = cmul(crs, cmul(V00, cconj(V10)));
        cf t1 = cmul(crs, cmul(V01, cconj(V11)));
        g_Pw[p] = cabs2(V00)+cabs2(V10)+2.f*t0.r + cabs2(V01)+cabs2(V11)+2.f*t1.r;
    }
}

// ---------------- K6: output ----------------
__global__ void k6_out(float* __restrict__ out){
    int q = blockIdx.x*8 + (threadIdx.x >> 5);
    int l = threadIdx.x & 31;
    int n2 = q >> 12;
    int b3 = q & 4095;
    float sc = 1.41421356237f / sqrtf(g_Pw[b3*32 + n2]);
    float4 v0 = g_V[2*q], v1 = g_V[2*q+1];
    cf V00{v0.x,v0.y}, V01{v0.z,v0.w}, V10{v1.x,v1.y}, V11{v1.z,v1.w};
    const float4* frf = g_FRF + b3*64;
    float* baseR = out + (size_t)b3*8192 + n2*128;
    float* baseI = baseR + 4096;
    float4 fa = frf[2*l], fb = frf[2*l+1];
    cf fa0{fa.x,fa.y}, fa1{fa.z,fa.w}, fb0{fb.x,fb.y}, fb1{fb.z,fb.w};
    cf oa0 = cadd(cmul(fa0,V00), cmul(fa1,V10));
    cf oa1 = cadd(cmul(fa0,V01), cmul(fa1,V11));
    cf ob0 = cadd(cmul(fb0,V00), cmul(fb1,V10));
    cf ob1 = cadd(cmul(fb0,V01), cmul(fb1,V11));
    ((float4*)baseR)[l] = make_float4(sc*oa0.r, sc*oa1.r, sc*ob0.r, sc*ob1.r);
    ((float4*)baseI)[l] = make_float4(sc*oa0.i, sc*oa1.i, sc*ob0.i, sc*ob1.i);
}

// ---------------- launch ----------------
extern "C" void kernel_launch(void* const* d_in, const int* in_sizes, int n_in,
                              void* d_out, int out_size){
    const float* H  = (const float*)d_in[0];
    const float* W0 = (const float*)d_in[1]; const float* b0 = (const float*)d_in[2];
    const float* W1 = (const float*)d_in[3]; const float* b1 = (const float*)d_in[4];
    const float* W2 = (const float*)d_in[5]; const float* b2 = (const float*)d_in[6];
    const float* W3 = (const float*)d_in[7]; const float* b3 = (const float*)d_in[8];
    cudaFuncSetAttribute(k3_mma, cudaFuncAttributeMaxDynamicSharedMemorySize, K3_SMEM);

    k_init<<<1,1>>>();
    k_wsplit<<<512,256>>>(W1, W2);
    k1_frf<<<BATCHN,64>>>(H);
    k2_hequ<<<16384,256>>>(H);
    k3_mma<<<1024,512,K3_SMEM>>>(W0, b0, b1, b2, W3, b3);
    k_bis<<<256,256>>>();
    k6_out<<<16384,256>>>((float*)d_out);
}

// round 12
// speedup vs baseline: 1.3578x; 1.3578x over previous
#include <cuda_runtime.h>
#include <cuda_bf16.h>
#include <cuda_pipeline.h>
#include <cstdint>

#define BATCHN 4096
#define NCC    32
#define NTT    64
#define NP     (BATCHN*NCC)   // 131072

// ---------------- scratch (static device globals; no allocation) ----------------
__device__ float4 g_FRF[BATCHN*NTT];
__device__ float4 g_colsum[BATCHN];
__device__ float2 g_cross[BATCHN];
__device__ float4 g_Hc[NP*2];
__device__ float  g_xin[NP*8];
__device__ float  g_xout[NP*8];
__device__ float4 g_V[NP*2];
__device__ float  g_Pw[NP];
__device__ float  g_part15[256][16];
__device__ float  g_sum15[5][16];
__device__ int    g_dec5[5];
__device__ unsigned g_ticket;
// bf16 hi/lo split weights, chunk-major layout: [kchunk(16)][n(256)][kk(16)]
__device__ __nv_bfloat16 g_W1hi[65536], g_W1lo[65536], g_W2hi[65536], g_W2lo[65536];

// ---------------- complex helpers ----------------
struct cf { float r, i; };
__device__ __forceinline__ cf cmul(cf a, cf b){ return {a.r*b.r - a.i*b.i, a.r*b.i + a.i*b.r}; }
__device__ __forceinline__ cf cadd(cf a, cf b){ return {a.r+b.r, a.i+b.i}; }
__device__ __forceinline__ cf csub(cf a, cf b){ return {a.r-b.r, a.i-b.i}; }
__device__ __forceinline__ cf cconj(cf a){ return {a.r, -a.i}; }
__device__ __forceinline__ float cabs2(cf a){ return a.r*a.r + a.i*a.i; }

// ---------------- warp mma helpers (plain sm_100 PTX) ----------------
__device__ __forceinline__ uint32_t smem_u32(const void* p){
    uint32_t a;
    asm("{ .reg .u64 t; cvta.to.shared.u64 t, %1; cvt.u32.u64 %0, t; }" : "=r"(a) : "l"(p));
    return a;
}
__device__ __forceinline__ void ldsm4(uint32_t* r, uint32_t addr){
    asm volatile("ldmatrix.sync.aligned.m8n8.x4.shared.b16 {%0,%1,%2,%3},[%4];"
                 : "=r"(r[0]),"=r"(r[1]),"=r"(r[2]),"=r"(r[3]) : "r"(addr));
}
__device__ __forceinline__ void mma_bf16(float* c, const uint32_t* a, const uint32_t* b){
    asm volatile("mma.sync.aligned.m16n8k16.row.col.f32.bf16.bf16.f32 "
                 "{%0,%1,%2,%3},{%4,%5,%6,%7},{%8,%9},{%0,%1,%2,%3};"
                 : "+f"(c[0]),"+f"(c[1]),"+f"(c[2]),"+f"(c[3])
                 : "r"(a[0]),"r"(a[1]),"r"(a[2]),"r"(a[3]), "r"(b[0]),"r"(b[1]));
}
__device__ __forceinline__ uint32_t pack_bf16x2(float even, float odd){
    uint32_t r;
    asm("cvt.rn.bf16x2.f32 %0, %1, %2;" : "=r"(r) : "f"(odd), "f"(even));  // low=even, high=odd
    return r;
}

// ---------------- K1: F_RF + column sums + cross ----------------
__global__ void k1_frf(const float* __restrict__ H){
    int b = blockIdx.x;
    int t = threadIdx.x;     // 64 threads
    const float* r0 = H + ((size_t)(b*2+0)*32 + 16)*128;
    const float* r1 = H + ((size_t)(b*2+1)*32 + 16)*128;
    float h0a = r0[0], h0b = r1[0];
    float hra = r0[t], hrb = r1[t];
    float inva = 1.0f/(8.0f*sqrtf(hra*hra + h0a*h0a));
    float invb = 1.0f/(8.0f*sqrtf(hrb*hrb + h0b*h0b));
    float f0r =  hra*inva, f0i = -h0a*inva;
    float f1r =  hrb*invb, f1i = -h0b*invb;
    g_FRF[b*64+t] = make_float4(f0r, f0i, f1r, f1i);
    float cr = f0r*f1r + f0i*f1i;
    float ci = f0i*f1r - f0r*f1i;
    __shared__ float s[6*64];
    s[0*64+t]=f0r; s[1*64+t]=f0i; s[2*64+t]=f1r; s[3*64+t]=f1i; s[4*64+t]=cr; s[5*64+t]=ci;
    __syncthreads();
    for (int off=32; off>=1; off>>=1){
        if (t < off){
            #pragma unroll
            for (int i=0;i<6;i++) s[i*64+t] += s[i*64+t+off];
        }
        __syncthreads();
    }
    if (t==0){
        g_colsum[b] = make_float4(s[0], s[64], s[128], s[192]);
        g_cross[b]  = make_float2(s[256], s[320]);
    }
}

// ---------------- K2: H_equ (normalized) + MLP input (smem reduction) ----------------
__global__ void k2_hequ(const float* __restrict__ H){
    __shared__ float4 sfrf[64];
    __shared__ float4 scs;
    __shared__ float sred[8*288];    // 8 warps x (32 lanes x 9 padded)
    __shared__ float ssum[64];
    int b2 = blockIdx.x >> 2;
    int g  = blockIdx.x & 3;
    int tid = threadIdx.x;
    if (tid < 64) sfrf[tid] = g_FRF[b2*64 + tid];
    if (tid == 64) scs = g_colsum[b2];
    __syncthreads();
    int w = tid >> 5, l = tid & 31;
    int p = (g*8 + w)*4096 + b2;
    const float* r0 = H + (size_t)(2*p)*128;
    const float* r1 = r0 + 128;
    float a00r=0,a00i=0,a01r=0,a01i=0,a10r=0,a10i=0,a11r=0,a11i=0;
    #pragma unroll
    for (int k=0;k<2;k++){
        int tt = l + k*32;
        float4 f = sfrf[tt];
        float x0 = r0[tt], x1 = r1[tt];
        a00r += x0*f.x; a00i += x0*f.y; a01r += x0*f.z; a01i += x0*f.w;
        a10r += x1*f.x; a10i += x1*f.y; a11r += x1*f.z; a11i += x1*f.w;
    }
    float* dst = &sred[w*288 + l*9];
    dst[0]=a00r; dst[1]=a00i; dst[2]=a01r; dst[3]=a01i;
    dst[4]=a10r; dst[5]=a10i; dst[6]=a11r; dst[7]=a11i;
    __syncthreads();
    if (tid < 64){
        int w2 = tid >> 3, v = tid & 7;
        float s = 0.f;
        #pragma unroll
        for (int ll = 0; ll < 32; ll++) s += sred[w2*288 + ll*9 + v];
        ssum[tid] = s;
    }
    __syncthreads();
    if (tid < 8){
        int p2 = (g*8 + tid)*4096 + b2;
        const float* q0 = H + (size_t)(2*p2)*128;
        float h00 = q0[0], h01 = q0[128];
        float b00r=ssum[tid*8+0], b00i=ssum[tid*8+1], b01r=ssum[tid*8+2], b01i=ssum[tid*8+3];
        float b10r=ssum[tid*8+4], b10i=ssum[tid*8+5], b11r=ssum[tid*8+6], b11i=ssum[tid*8+7];
        float4 cs = scs;
        float m00r = b00r - h00*cs.y, m00i = b00i + h00*cs.x;
        float m01r = b01r - h00*cs.w, m01i = b01i + h00*cs.z;
        float m10r = b10r - h01*cs.y, m10i = b10i + h01*cs.x;
        float m11r = b11r - h01*cs.w, m11i = b11i + h01*cs.z;
        float pw = m00r*m00r+m00i*m00i+m01r*m01r+m01i*m01i
                 + m10r*m10r+m10i*m10i+m11r*m11r+m11i*m11i;
        float inv = 1.0f/sqrtf(pw);
        m00r*=inv; m00i*=inv; m01r*=inv; m01i*=inv;
        m10r*=inv; m10i*=inv; m11r*=inv; m11i*=inv;
        g_Hc[2*p2]   = make_float4(m00r,m00i,m01r,m01i);
        g_Hc[2*p2+1] = make_float4(m10r,m10i,m11r,m11i);
        float* xo = g_xin + (size_t)p2*8;
        xo[0]=m00r; xo[1]=m01r; xo[2]=m10r; xo[3]=m11r;
        xo[4]=m00i; xo[5]=m01i; xo[6]=m10i; xo[7]=m11i;
    }
}

// ---------------- weight split (+ bisection state init) ----------------
__global__ void k_wsplit(const float* __restrict__ W1, const float* __restrict__ W2){
    if (blockIdx.x == 0 && threadIdx.x == 0){
        g_ticket = 0u;
        for (int i = 0; i < 5; i++) g_dec5[i] = 0;
    }
    int idx = blockIdx.x*256 + threadIdx.x;     // 0..131071
    int layer = idx >> 16;
    int e = idx & 65535;
    int n = e & 255, k = e >> 8;
    float v = (layer ? W2 : W1)[k*256 + n];
    __nv_bfloat16 h = __float2bfloat16(v);
    __nv_bfloat16 l = __float2bfloat16(v - __bfloat162float(h));
    int pos = (k >> 4)*4096 + n*16 + (k & 15);
    if (layer){ g_W2hi[pos] = h; g_W2lo[pos] = l; }
    else      { g_W1hi[pos] = h; g_W1lo[pos] = l; }
}

// ---------------- K3: mma.sync bf16x3 fused MLP (R8-proven, 256 threads) ----------------
#define SA_HI   0          // 128 rows x 264 halves (stride 528B) = 67584
#define SA_LO   67584
#define SW_OFF  135168     // 2 buf x (hi 12288 + lo 12288) = 49152
#define SW0_OFF 184320
#define SW3_OFF 192512
#define SB0_OFF 200704
#define SB1_OFF 201728
#define SB2_OFF 202752
#define SB3_OFF 203776
#define K3_SMEM 203904

__device__ __forceinline__ void issue_w(char* sm, int layer, int c, int buf, int tid){
    const __nv_bfloat16* gh = layer ? g_W2hi : g_W1hi;
    const __nv_bfloat16* gl = layer ? g_W2lo : g_W1lo;
    char* dhi = sm + SW_OFF + buf*24576;
    char* dlo = dhi + 12288;
    #pragma unroll
    for (int j = 0; j < 2; j++){
        int u = tid + j*256;
        int n = u >> 1, h8 = u & 1;
        __pipeline_memcpy_async(dhi + n*48 + h8*16, gh + c*4096 + n*16 + h8*8, 16);
        __pipeline_memcpy_async(dlo + n*48 + h8*16, gl + c*4096 + n*16 + h8*8, 16);
    }
    __pipeline_commit();
}

__global__ void __launch_bounds__(256, 1) k3_mma(
        const float* __restrict__ W0, const float* __restrict__ b0v,
        const float* __restrict__ b1v, const float* __restrict__ b2v,
        const float* __restrict__ W3, const float* __restrict__ b3v){
    extern __shared__ char sm[];
    uint32_t sbase = smem_u32(sm);
    int tid  = threadIdx.x;
    int wid  = tid >> 5, lane = tid & 31;
    int wm   = wid >> 2;        // rowgroup 0..1 (64 rows)
    int wn   = wid & 3;         // ngroup  0..3 (64 cols)

    issue_w(sm, 0, 0, 0, tid);
    issue_w(sm, 0, 1, 1, tid);

    float* sW0 = (float*)(sm + SW0_OFF);
    float* sW3 = (float*)(sm + SW3_OFF);
    float* sB0 = (float*)(sm + SB0_OFF);
    float* sB1 = (float*)(sm + SB1_OFF);
    float* sB2 = (float*)(sm + SB2_OFF);
    float* sB3 = (float*)(sm + SB3_OFF);
    #pragma unroll
    for (int i = tid; i < 2048; i += 256){ sW0[i] = W0[i]; sW3[i] = W3[i]; }
    if (tid < 256){ sB0[tid] = b0v[tid]; sB1[tid] = b1v[tid]; sB2[tid] = b2v[tid]; }
    if (tid < 8) sB3[tid] = b3v[tid];

    // ---- layer0: 8 -> 256 FFMA, split, write SA ----
    int r = tid >> 1, h = tid & 1;
    int grow = blockIdx.x*128 + r;
    float xr[8];
    {
        float4 a = *(const float4*)(g_xin + (size_t)grow*8);
        float4 b = *(const float4*)(g_xin + (size_t)grow*8 + 4);
        xr[0]=a.x; xr[1]=a.y; xr[2]=a.z; xr[3]=a.w;
        xr[4]=b.x; xr[5]=b.y; xr[6]=b.z; xr[7]=b.w;
    }
    __syncthreads();
    {
        char* rowh = sm + SA_HI + r*528;
        char* rowl = sm + SA_LO + r*528;
        #pragma unroll 4
        for (int cc = 0; cc < 64; cc++){
            int c0 = h*128 + 2*cc;
            float e = sB0[c0], o = sB0[c0+1];
            #pragma unroll
            for (int i = 0; i < 8; i++){
                e += xr[i]*sW0[i*256 + c0];
                o += xr[i]*sW0[i*256 + c0 + 1];
            }
            e = fmaxf(e, 0.f); o = fmaxf(o, 0.f);
            uint32_t hi = pack_bf16x2(e, o);
            float eh = __uint_as_float(hi << 16);
            float oh = __uint_as_float(hi & 0xffff0000u);
            uint32_t lo = pack_bf16x2(e - eh, o - oh);
            *(uint32_t*)(rowh + c0*2) = hi;
            *(uint32_t*)(rowl + c0*2) = lo;
        }
    }
    __syncthreads();

    // ---- layers 1,2: mma ----
    float acc[128];
    #pragma unroll
    for (int i = 0; i < 128; i++) acc[i] = 0.f;

    int arow   = wm*64 + (lane & 15);
    uint32_t aoff = (uint32_t)arow*528 + ((lane >> 4) & 1)*16;
    int nrow   = wn*64 + (lane & 7) + ((lane & 16) >> 1);
    uint32_t boff = (uint32_t)nrow*48 + ((lane >> 3) & 1)*16;

    #pragma unroll 1
    for (int layer = 0; layer < 2; layer++){
        #pragma unroll 1
        for (int c = 0; c < 16; c++){
            if (c < 15) __pipeline_wait_prior(1);
            else        __pipeline_wait_prior(0);
            __syncthreads();
            int buf = c & 1;
            uint32_t wbh = sbase + SW_OFF + buf*24576 + boff;
            uint32_t wbl = wbh + 12288;
            uint32_t bh[16], bl[16];
            #pragma unroll
            for (int ntp = 0; ntp < 4; ntp++){
                ldsm4(&bh[ntp*4], wbh + ntp*768);
                ldsm4(&bl[ntp*4], wbl + ntp*768);
            }
            uint32_t abase = sbase + aoff + (uint32_t)c*32;
            uint32_t ah[16], al[16];
            #pragma unroll
            for (int mf = 0; mf < 4; mf++){
                ldsm4(&ah[mf*4], abase + SA_HI + mf*8448);
                ldsm4(&al[mf*4], abase + SA_LO + mf*8448);
            }
            #pragma unroll
            for (int prod = 0; prod < 3; prod++){
                const uint32_t* A  = (prod == 1) ? al : ah;
                const uint32_t* Bf = (prod == 2) ? bl : bh;
                #pragma unroll
                for (int mf = 0; mf < 4; mf++){
                    #pragma unroll
                    for (int nt = 0; nt < 8; nt++){
                        mma_bf16(&acc[(mf*8 + nt)*4], &A[mf*4],
                                 &Bf[(nt >> 1)*4 + (nt & 1)*2]);
                    }
                }
            }
            __syncthreads();
            if (c + 2 < 16) issue_w(sm, layer, c + 2, c & 1, tid);
        }
        if (layer == 0){
            issue_w(sm, 1, 0, 0, tid);
            issue_w(sm, 1, 1, 1, tid);
        }
        const float* sb = layer ? sB2 : sB1;
        int erow = wm*64 + (lane >> 2);
        int ecol = wn*64 + (lane & 3)*2;
        #pragma unroll
        for (int mf = 0; mf < 4; mf++){
            #pragma unroll
            for (int nt = 0; nt < 8; nt++){
                float* C = &acc[(mf*8 + nt)*4];
                int col = ecol + nt*8;
                float bv0 = sb[col], bv1 = sb[col+1];
                #pragma unroll
                for (int half = 0; half < 2; half++){
                    int row = erow + mf*16 + half*8;
                    float v0 = fmaxf(C[half*2]   + bv0, 0.f);
                    float v1 = fmaxf(C[half*2+1] + bv1, 0.f);
                    uint32_t hi = pack_bf16x2(v0, v1);
                    float eh = __uint_as_float(hi << 16);
                    float oh = __uint_as_float(hi & 0xffff0000u);
                    uint32_t lo = pack_bf16x2(v0 - eh, v1 - oh);
                    *(uint32_t*)(sm + SA_HI + row*528 + col*2) = hi;
                    *(uint32_t*)(sm + SA_LO + row*528 + col*2) = lo;
                    C[half*2] = 0.f; C[half*2+1] = 0.f;
                }
            }
        }
        __syncthreads();
    }

    // ---- layer3: 256 -> 8 FFMA from SA ----
    {
        float a3[8];
        #pragma unroll
        for (int cc = 0; cc < 8; cc++) a3[cc] = 0.f;
        char* rowh = sm + SA_HI + r*528;
        char* rowl = sm + SA_LO + r*528;
        #pragma unroll 4
        for (int kk = 0; kk < 64; kk++){
            int k = h*128 + 2*kk;
            uint32_t wh = *(uint32_t*)(rowh + k*2);
            uint32_t wl = *(uint32_t*)(rowl + k*2);
            float v0 = __uint_as_float(wh << 16)          + __uint_as_float(wl << 16);
            float v1 = __uint_as_float(wh & 0xffff0000u)  + __uint_as_float(wl & 0xffff0000u);
            #pragma unroll
            for (int cc = 0; cc < 8; cc++){
                a3[cc] += v0*sW3[k*8 + cc] + v1*sW3[(k+1)*8 + cc];
            }
        }
        #pragma unroll
        for (int cc = 0; cc < 8; cc++)
            a3[cc] += __shfl_xor_sync(0xffffffffu, a3[cc], 1);
        if (h == 0){
            float* xo = g_xout + (size_t)grow*8;
            #pragma unroll
            for (int cc = 0; cc < 8; cc++) xo[cc] = a3[cc] + sB3[cc];
        }
    }
}

// ---------------- K4 + bisection(4 steps/barrier) + K5 fused (R8-proven) ----------------
__global__ void __launch_bounds__(256, 2) k_bis(){
    int tid = threadIdx.x;
    int bid = blockIdx.x;
    int gid = bid*256 + tid;        // 0..65535
    int lane = tid & 31, wid = tid >> 5;

    float A0[2],A1[2],A2[2],Cc0[2],Cc1[2],Cc2[2],Cc3[2];
    float Bar[2],Bai[2],Bbr[2],Bbi[2],Bcr[2],Bci[2],Bdr[2],Bdi[2];
    float uwr0[2],uwi0[2],uwr1[2],uwi1[2];
    float hc[2][8];

    #pragma unroll
    for (int q = 0; q < 2; q++){
        int p = gid + q*65536;
        float4 hc0 = g_Hc[2*p], hc1 = g_Hc[2*p+1];
        hc[q][0]=hc0.x; hc[q][1]=hc0.y; hc[q][2]=hc0.z; hc[q][3]=hc0.w;
        hc[q][4]=hc1.x; hc[q][5]=hc1.y; hc[q][6]=hc1.z; hc[q][7]=hc1.w;
        const float* x = g_xout + (size_t)p*8;
        float x0=x[0],x1=x[1],x2=x[2],x3=x[3],x4=x[4],x5=x[5],x6=x[6],x7=x[7];
        cf U0{x0,x2}, U1{x1,x3}, Wm0{x4,x6}, Wm1{x5,x7};
        float au0 = x0*x0 + x2*x2, au1 = x1*x1 + x3*x3;
        cf c0{Wm0.r*au0, Wm0.i*au0}, c1{Wm1.r*au1, Wm1.i*au1};
        cf h00{hc0.x,hc0.y}, h01{hc0.z,hc0.w}, h10{hc1.x,hc1.y}, h11{hc1.z,hc1.w};
        float n00 = cabs2(h00), n01 = cabs2(h01), n10 = cabs2(h10), n11 = cabs2(h11);
        cf Ba{c0.r*n00 + c1.r*n10, c0.i*n00 + c1.i*n10};
        cf Bd{c0.r*n01 + c1.r*n11, c0.i*n01 + c1.i*n11};
        cf Bb = cadd(cmul(c0, cmul(cconj(h00), h01)), cmul(c1, cmul(cconj(h10), h11)));
        cf Bc = cadd(cmul(c0, cmul(cconj(h01), h00)), cmul(c1, cmul(cconj(h11), h10)));
        cf uw0 = cmul(U0, Wm0), uw1 = cmul(U1, Wm1);
        cf g00 = cconj(h00), g01 = cconj(h01), g10 = cconj(h10), g11 = cconj(h11);
        cf p00 = csub(cmul(Bd,g00), cmul(Bb,g01));
        cf p01 = csub(cmul(Ba,g01), cmul(Bc,g00));
        cf p10 = csub(cmul(Bd,g10), cmul(Bb,g11));
        cf p11 = csub(cmul(Ba,g11), cmul(Bc,g10));
        float u0 = cabs2(uw0), u1 = cabs2(uw1);
        A0[q] = u0*(cabs2(p00)+cabs2(p01)) + u1*(cabs2(p10)+cabs2(p11));
        A1[q] = 2.f*( u0*(p00.r*g00.r + p00.i*g00.i + p01.r*g01.r + p01.i*g01.i)
                    + u1*(p10.r*g10.r + p10.i*g10.i + p11.r*g11.r + p11.i*g11.i) );
        A2[q] = u0*(cabs2(g00)+cabs2(g01)) + u1*(cabs2(g10)+cabs2(g11));
        cf T = cadd(Ba, Bd);
        cf D = csub(cmul(Ba,Bd), cmul(Bb,Bc));
        Cc0[q] = cabs2(D);
        Cc1[q] = 2.f*(T.r*D.r + T.i*D.i);
        Cc2[q] = T.r*T.r + T.i*T.i + 2.f*D.r;
        Cc3[q] = 2.f*T.r;
        Bar[q]=Ba.r; Bai[q]=Ba.i; Bbr[q]=Bb.r; Bbi[q]=Bb.i;
        Bcr[q]=Bc.r; Bci[q]=Bc.i; Bdr[q]=Bd.r; Bdi[q]=Bd.i;
        uwr0[q]=uw0.r; uwi0[q]=uw0.i; uwr1[q]=uw1.r; uwi1[q]=uw1.i;
    }

    __shared__ float swarp[8][16];
    __shared__ float spart[16][16];
    __shared__ float ssum[16];
    __shared__ int   slast;
    float lo = 0.f, hi = 10.f, mu = 5.f;

    #pragma unroll 1
    for (int round = 0; round < 5; round++){
        float L[16], Hh[16], m[16];
        L[1] = lo; Hh[1] = hi;
        #pragma unroll
        for (int i = 1; i < 8; i++){
            m[i] = 0.5f*(L[i] + Hh[i]);
            L[2*i] = L[i];  Hh[2*i] = m[i];
            L[2*i+1] = m[i]; Hh[2*i+1] = Hh[i];
        }
        #pragma unroll
        for (int i = 8; i < 16; i++) m[i] = 0.5f*(L[i] + Hh[i]);

        float v[15];
        #pragma unroll
        for (int node = 1; node <= 15; node++){
            float s = 2.0f*m[node];
            float a = 0.f;
            #pragma unroll
            for (int q = 0; q < 2; q++){
                float num = A0[q] + s*(A1[q] + s*A2[q]);
                float den = Cc0[q] + s*(Cc1[q] + s*(Cc2[q] + s*(Cc3[q] + s)));
                a += num/den;
            }
            v[node-1] = a;
        }
        #pragma unroll
        for (int j = 0; j < 15; j++){
            #pragma unroll
            for (int off = 16; off; off >>= 1)
                v[j] += __shfl_down_sync(0xffffffffu, v[j], off);
            if (lane == 0) swarp[wid][j] = v[j];
        }
        __syncthreads();
        if (tid < 15){
            float s = 0.f;
            #pragma unroll
            for (int w = 0; w < 8; w++) s += swarp[w][tid];
            g_part15[bid][tid] = s;
        }
        __threadfence();
        __syncthreads();
        if (tid == 0){
            unsigned old = atomicAdd(&g_ticket, 1u);
            slast = (old == (unsigned)(256*(round+1) - 1)) ? 1 : 0;
        }
        __syncthreads();
        if (slast){
            int j = tid & 15, chunk = tid >> 4;
            float sacc = 0.f;
            if (j < 15){
                volatile float* gp = &g_part15[0][0];
                int base = chunk*16;
                #pragma unroll
                for (int i = 0; i < 16; i++) sacc += gp[(base + i)*16 + j];
            }
            spart[chunk][j] = sacc;
            __syncthreads();
            if (tid < 15){
                float s = 0.f;
                #pragma unroll
                for (int cc = 0; cc < 16; cc++) s += spart[cc][tid];
                g_sum15[round][tid] = s;
            }
            __threadfence();
            __syncthreads();
            if (tid == 0){ g_dec5[round] = 1; __threadfence(); }
        }
        if (tid == 0){
            volatile int* dp = (volatile int*)&g_dec5[round];
            int d;
            do { d = *dp; } while (d == 0);
            __threadfence();
            volatile float* gs = &g_sum15[round][0];
            #pragma unroll
            for (int j = 0; j < 15; j++) ssum[j] = gs[j];
        }
        __syncthreads();
        float Lc = lo, Hc = hi;
        int node = 1;
        #pragma unroll
        for (int st = 0; st < 4; st++){
            float mm = 0.5f*(Lc + Hc);
            float S = ssum[node-1];
            mu = mm;
            if (S > 1.0f){ Lc = mm; node = 2*node + 1; }
            else         { Hc = mm; node = 2*node; }
        }
        lo = Lc; hi = Hc;
        __syncthreads();
    }

    // epilogue: final V + per-item power
    float s = 2.0f*mu;
    #pragma unroll
    for (int q = 0; q < 2; q++){
        int p = gid + q*65536;
        cf a{Bar[q] + s, Bai[q]}, b{Bbr[q], Bbi[q]}, c{Bcr[q], Bci[q]}, d{Bdr[q] + s, Bdi[q]};
        cf det = csub(cmul(a,d), cmul(b,c));
        float id = 1.0f/cabs2(det);
        cf idet{det.r*id, -det.i*id};
        cf g00{hc[q][0],-hc[q][1]}, g01{hc[q][2],-hc[q][3]};
        cf g10{hc[q][4],-hc[q][5]}, g11{hc[q][6],-hc[q][7]};
        cf y00 = cmul(csub(cmul(d,g00), cmul(b,g01)), idet);
        cf y01 = cmul(csub(cmul(a,g01), cmul(c,g00)), idet);
        cf y10 = cmul(csub(cmul(d,g10), cmul(b,g11)), idet);
        cf y11 = cmul(csub(cmul(a,g11), cmul(c,g10)), idet);
        cf uw0{uwr0[q],uwi0[q]}, uw1{uwr1[q],uwi1[q]};
        cf V00 = cmul(uw0,y00);
        cf V01 = cmul(uw1,y10);
        cf V10 = cmul(uw0,y01);
        cf V11 = cmul(uw1,y11);
        g_V[2*p]   = make_float4(V00.r,V00.i,V01.r,V01.i);
        g_V[2*p+1] = make_float4(V10.r,V10.i,V11.r,V11.i);
        float2 cr = g_cross[p & 4095];
        cf crs{cr.x, cr.y};
        cf t0 = cmul(crs, cmul(V00, cconj(V10)));
        cf t1 = cmul(crs, cmul(V01, cconj(V11)));
        g_Pw[p] = cabs2(V00)+cabs2(V10)+2.f*t0.r + cabs2(V01)+cabs2(V11)+2.f*t1.r;
    }
}

// ---------------- K6: output ----------------
__global__ void k6_out(float* __restrict__ out){
    int q = blockIdx.x*8 + (threadIdx.x >> 5);
    int l = threadIdx.x & 31;
    int n2 = q >> 12;
    int b3 = q & 4095;
    float sc = 1.41421356237f / sqrtf(g_Pw[b3*32 + n2]);
    float4 v0 = g_V[2*q], v1 = g_V[2*q+1];
    cf V00{v0.x,v0.y}, V01{v0.z,v0.w}, V10{v1.x,v1.y}, V11{v1.z,v1.w};
    const float4* frf = g_FRF + b3*64;
    float* baseR = out + (size_t)b3*8192 + n2*128;
    float* baseI = baseR + 4096;
    float4 fa = frf[2*l], fb = frf[2*l+1];
    cf fa0{fa.x,fa.y}, fa1{fa.z,fa.w}, fb0{fb.x,fb.y}, fb1{fb.z,fb.w};
    cf oa0 = cadd(cmul(fa0,V00), cmul(fa1,V10));
    cf oa1 = cadd(cmul(fa0,V01), cmul(fa1,V11));
    cf ob0 = cadd(cmul(fb0,V00), cmul(fb1,V10));
    cf ob1 = cadd(cmul(fb0,V01), cmul(fb1,V11));
    ((float4*)baseR)[l] = make_float4(sc*oa0.r, sc*oa1.r, sc*ob0.r, sc*ob1.r);
    ((float4*)baseI)[l] = make_float4(sc*oa0.i, sc*oa1.i, sc*ob0.i, sc*ob1.i);
}

// ---------------- launch ----------------
extern "C" void kernel_launch(void* const* d_in, const int* in_sizes, int n_in,
                              void* d_out, int out_size){
    const float* H  = (const float*)d_in[0];
    const float* W0 = (const float*)d_in[1]; const float* b0 = (const float*)d_in[2];
    const float* W1 = (const float*)d_in[3]; const float* b1 = (const float*)d_in[4];
    const float* W2 = (const float*)d_in[5]; const float* b2 = (const float*)d_in[6];
    const float* W3 = (const float*)d_in[7]; const float* b3 = (const float*)d_in[8];
    cudaFuncSetAttribute(k3_mma, cudaFuncAttributeMaxDynamicSharedMemorySize, K3_SMEM);

    k_wsplit<<<512,256>>>(W1, W2);
    k1_frf<<<BATCHN,64>>>(H);
    k2_hequ<<<16384,256>>>(H);
    k3_mma<<<1024,256,K3_SMEM>>>(W0, b0, b1, b2, W3, b3);
    k_bis<<<256,256>>>();
    k6_out<<<16384,256>>>((float*)d_out);
}

// round 14
// speedup vs baseline: 1.4518x; 1.0692x over previous
#include <cuda_runtime.h>
#include <cuda_bf16.h>
#include <cuda_pipeline.h>
#include <cstdint>

#define BATCHN 4096
#define NCC    32
#define NTT    64
#define NP     (BATCHN*NCC)   // 131072

// ---------------- scratch (static device globals; no allocation) ----------------
__device__ float4 g_FRF[BATCHN*NTT];
__device__ float4 g_colsum[BATCHN];
__device__ float2 g_cross[BATCHN];
__device__ float4 g_Hc[NP*2];
__device__ float  g_xin[NP*8];
__device__ float  g_xout[NP*8];
__device__ float4 g_V[NP*2];
__device__ float  g_Pw[NP];
__device__ float  g_part15[256][16];
__device__ float  g_sum15[5][16];
__device__ int    g_dec5[5];
__device__ unsigned g_ticket;
// bf16 hi/lo split weights, chunk-major layout: [kchunk(16)][n(256)][kk(16)]
__device__ __nv_bfloat16 g_W1hi[65536], g_W1lo[65536], g_W2hi[65536], g_W2lo[65536];

// ---------------- complex helpers ----------------
struct cf { float r, i; };
__device__ __forceinline__ cf cmul(cf a, cf b){ return {a.r*b.r - a.i*b.i, a.r*b.i + a.i*b.r}; }
__device__ __forceinline__ cf cadd(cf a, cf b){ return {a.r+b.r, a.i+b.i}; }
__device__ __forceinline__ cf csub(cf a, cf b){ return {a.r-b.r, a.i-b.i}; }
__device__ __forceinline__ cf cconj(cf a){ return {a.r, -a.i}; }
__device__ __forceinline__ float cabs2(cf a){ return a.r*a.r + a.i*a.i; }

// ---------------- warp mma helpers (plain sm_100 PTX) ----------------
__device__ __forceinline__ uint32_t smem_u32(const void* p){
    uint32_t a;
    asm("{ .reg .u64 t; cvta.to.shared.u64 t, %1; cvt.u32.u64 %0, t; }" : "=r"(a) : "l"(p));
    return a;
}
__device__ __forceinline__ void ldsm4(uint32_t* r, uint32_t addr){
    asm volatile("ldmatrix.sync.aligned.m8n8.x4.shared.b16 {%0,%1,%2,%3},[%4];"
                 : "=r"(r[0]),"=r"(r[1]),"=r"(r[2]),"=r"(r[3]) : "r"(addr));
}
__device__ __forceinline__ void mma_bf16(float* c, const uint32_t* a, const uint32_t* b){
    asm volatile("mma.sync.aligned.m16n8k16.row.col.f32.bf16.bf16.f32 "
                 "{%0,%1,%2,%3},{%4,%5,%6,%7},{%8,%9},{%0,%1,%2,%3};"
                 : "+f"(c[0]),"+f"(c[1]),"+f"(c[2]),"+f"(c[3])
                 : "r"(a[0]),"r"(a[1]),"r"(a[2]),"r"(a[3]), "r"(b[0]),"r"(b[1]));
}
__device__ __forceinline__ uint32_t pack_bf16x2(float even, float odd){
    uint32_t r;
    asm("cvt.rn.bf16x2.f32 %0, %1, %2;" : "=r"(r) : "f"(odd), "f"(even));  // low=even, high=odd
    return r;
}
#define PAIRBAR(id) asm volatile("bar.sync %0, 64;" :: "r"(id) : "memory")

// ---------------- K1: F_RF + column sums + cross ----------------
__global__ void k1_frf(const float* __restrict__ H){
    int b = blockIdx.x;
    int t = threadIdx.x;     // 64 threads
    const float* r0 = H + ((size_t)(b*2+0)*32 + 16)*128;
    const float* r1 = H + ((size_t)(b*2+1)*32 + 16)*128;
    float h0a = r0[0], h0b = r1[0];
    float hra = r0[t], hrb = r1[t];
    float inva = 1.0f/(8.0f*sqrtf(hra*hra + h0a*h0a));
    float invb = 1.0f/(8.0f*sqrtf(hrb*hrb + h0b*h0b));
    float f0r =  hra*inva, f0i = -h0a*inva;
    float f1r =  hrb*invb, f1i = -h0b*invb;
    g_FRF[b*64+t] = make_float4(f0r, f0i, f1r, f1i);
    float cr = f0r*f1r + f0i*f1i;
    float ci = f0i*f1r - f0r*f1i;
    __shared__ float s[6*64];
    s[0*64+t]=f0r; s[1*64+t]=f0i; s[2*64+t]=f1r; s[3*64+t]=f1i; s[4*64+t]=cr; s[5*64+t]=ci;
    __syncthreads();
    for (int off=32; off>=1; off>>=1){
        if (t < off){
            #pragma unroll
            for (int i=0;i<6;i++) s[i*64+t] += s[i*64+t+off];
        }
        __syncthreads();
    }
    if (t==0){
        g_colsum[b] = make_float4(s[0], s[64], s[128], s[192]);
        g_cross[b]  = make_float2(s[256], s[320]);
    }
}

// ---------------- K2: H_equ (normalized) + MLP input (smem reduction, R12-proven) ----------------
__global__ void k2_hequ(const float* __restrict__ H){
    __shared__ float4 sfrf[64];
    __shared__ float4 scs;
    __shared__ float sred[8*288];
    __shared__ float ssum[64];
    int b2 = blockIdx.x >> 2;
    int g  = blockIdx.x & 3;
    int tid = threadIdx.x;
    if (tid < 64) sfrf[tid] = g_FRF[b2*64 + tid];
    if (tid == 64) scs = g_colsum[b2];
    __syncthreads();
    int w = tid >> 5, l = tid & 31;
    int p = (g*8 + w)*4096 + b2;
    const float* r0 = H + (size_t)(2*p)*128;
    const float* r1 = r0 + 128;
    float a00r=0,a00i=0,a01r=0,a01i=0,a10r=0,a10i=0,a11r=0,a11i=0;
    #pragma unroll
    for (int k=0;k<2;k++){
        int tt = l + k*32;
        float4 f = sfrf[tt];
        float x0 = r0[tt], x1 = r1[tt];
        a00r += x0*f.x; a00i += x0*f.y; a01r += x0*f.z; a01i += x0*f.w;
        a10r += x1*f.x; a10i += x1*f.y; a11r += x1*f.z; a11i += x1*f.w;
    }
    float* dst = &sred[w*288 + l*9];
    dst[0]=a00r; dst[1]=a00i; dst[2]=a01r; dst[3]=a01i;
    dst[4]=a10r; dst[5]=a10i; dst[6]=a11r; dst[7]=a11i;
    __syncthreads();
    if (tid < 64){
        int w2 = tid >> 3, v = tid & 7;
        float s = 0.f;
        #pragma unroll
        for (int ll = 0; ll < 32; ll++) s += sred[w2*288 + ll*9 + v];
        ssum[tid] = s;
    }
    __syncthreads();
    if (tid < 8){
        int p2 = (g*8 + tid)*4096 + b2;
        const float* q0 = H + (size_t)(2*p2)*128;
        float h00 = q0[0], h01 = q0[128];
        float b00r=ssum[tid*8+0], b00i=ssum[tid*8+1], b01r=ssum[tid*8+2], b01i=ssum[tid*8+3];
        float b10r=ssum[tid*8+4], b10i=ssum[tid*8+5], b11r=ssum[tid*8+6], b11i=ssum[tid*8+7];
        float4 cs = scs;
        float m00r = b00r - h00*cs.y, m00i = b00i + h00*cs.x;
        float m01r = b01r - h00*cs.w, m01i = b01i + h00*cs.z;
        float m10r = b10r - h01*cs.y, m10i = b10i + h01*cs.x;
        float m11r = b11r - h01*cs.w, m11i = b11i + h01*cs.z;
        float pw = m00r*m00r+m00i*m00i+m01r*m01r+m01i*m01i
                 + m10r*m10r+m10i*m10i+m11r*m11r+m11i*m11i;
        float inv = 1.0f/sqrtf(pw);
        m00r*=inv; m00i*=inv; m01r*=inv; m01i*=inv;
        m10r*=inv; m10i*=inv; m11r*=inv; m11i*=inv;
        g_Hc[2*p2]   = make_float4(m00r,m00i,m01r,m01i);
        g_Hc[2*p2+1] = make_float4(m10r,m10i,m11r,m11i);
        float* xo = g_xin + (size_t)p2*8;
        xo[0]=m00r; xo[1]=m01r; xo[2]=m10r; xo[3]=m11r;
        xo[4]=m00i; xo[5]=m01i; xo[6]=m10i; xo[7]=m11i;
    }
}

// ---------------- weight split (+ bisection state init) ----------------
__global__ void k_wsplit(const float* __restrict__ W1, const float* __restrict__ W2){
    if (blockIdx.x == 0 && threadIdx.x == 0){
        g_ticket = 0u;
        for (int i = 0; i < 5; i++) g_dec5[i] = 0;
    }
    int idx = blockIdx.x*256 + threadIdx.x;     // 0..131071
    int layer = idx >> 16;
    int e = idx & 65535;
    int n = e & 255, k = e >> 8;
    float v = (layer ? W2 : W1)[k*256 + n];
    __nv_bfloat16 h = __float2bfloat16(v);
    __nv_bfloat16 l = __float2bfloat16(v - __bfloat162float(h));
    int pos = (k >> 4)*4096 + n*16 + (k & 15);
    if (layer){ g_W2hi[pos] = h; g_W2lo[pos] = l; }
    else      { g_W1hi[pos] = h; g_W1lo[pos] = l; }
}

// ---------------- K3: mma.sync bf16x3 fused MLP (256 thr, pair-scoped barriers) ----------------
#define SA_HI   0          // 128 rows x 264 halves (stride 528B) = 67584
#define SA_LO   67584
#define SW_OFF  135168     // 2 buf x (hi 12288 + lo 12288) = 49152
#define SW0_OFF 184320
#define SW3_OFF 192512
#define SB0_OFF 200704
#define SB1_OFF 201728
#define SB2_OFF 202752
#define SB3_OFF 203776
#define K3_SMEM 203904

// each pair (warps wn and wn+4) fills ONLY its own 64 B-rows of the buffer
__device__ __forceinline__ void issue_wp(char* sm, int layer, int c, int buf, int n){
    const __nv_bfloat16* gh = layer ? g_W2hi : g_W1hi;
    const __nv_bfloat16* gl = layer ? g_W2lo : g_W1lo;
    char* dhi = sm + SW_OFF + buf*24576 + n*48;
    char* dlo = dhi + 12288;
    const __nv_bfloat16* srch = gh + c*4096 + n*16;
    const __nv_bfloat16* srcl = gl + c*4096 + n*16;
    __pipeline_memcpy_async(dhi,      srch,     16);
    __pipeline_memcpy_async(dhi + 16, srch + 8, 16);
    __pipeline_memcpy_async(dlo,      srcl,     16);
    __pipeline_memcpy_async(dlo + 16, srcl + 8, 16);
    __pipeline_commit();
}

__global__ void __launch_bounds__(256, 1) k3_mma(
        const float* __restrict__ W0, const float* __restrict__ b0v,
        const float* __restrict__ b1v, const float* __restrict__ b2v,
        const float* __restrict__ W3, const float* __restrict__ b3v){
    extern __shared__ char sm[];
    uint32_t sbase = smem_u32(sm);
    int tid  = threadIdx.x;
    int wid  = tid >> 5, lane = tid & 31;
    int wm   = wid >> 2;        // rowgroup 0..1 (64 rows)
    int wn   = wid & 3;         // ngroup  0..3 (64 cols)
    int prow = wn*64 + wm*32 + lane;   // this thread's B-row (within pair region)
    int barid = 1 + wn;

    issue_wp(sm, 0, 0, 0, prow);
    issue_wp(sm, 0, 1, 1, prow);

    float* sW0 = (float*)(sm + SW0_OFF);
    float* sW3 = (float*)(sm + SW3_OFF);
    float* sB0 = (float*)(sm + SB0_OFF);
    float* sB1 = (float*)(sm + SB1_OFF);
    float* sB2 = (float*)(sm + SB2_OFF);
    float* sB3 = (float*)(sm + SB3_OFF);
    #pragma unroll
    for (int i = tid; i < 2048; i += 256){ sW0[i] = W0[i]; sW3[i] = W3[i]; }
    if (tid < 256){ sB0[tid] = b0v[tid]; sB1[tid] = b1v[tid]; sB2[tid] = b2v[tid]; }
    if (tid < 8) sB3[tid] = b3v[tid];

    // ---- layer0: 8 -> 256 FFMA, split, write SA ----
    int r = tid >> 1, h = tid & 1;
    int grow = blockIdx.x*128 + r;
    float xr[8];
    {
        float4 a = *(const float4*)(g_xin + (size_t)grow*8);
        float4 b = *(const float4*)(g_xin + (size_t)grow*8 + 4);
        xr[0]=a.x; xr[1]=a.y; xr[2]=a.z; xr[3]=a.w;
        xr[4]=b.x; xr[5]=b.y; xr[6]=b.z; xr[7]=b.w;
    }
    __syncthreads();
    {
        char* rowh = sm + SA_HI + r*528;
        char* rowl = sm + SA_LO + r*528;
        #pragma unroll 4
        for (int cc = 0; cc < 64; cc++){
            int c0 = h*128 + 2*cc;
            float e = sB0[c0], o = sB0[c0+1];
            #pragma unroll
            for (int i = 0; i < 8; i++){
                e += xr[i]*sW0[i*256 + c0];
                o += xr[i]*sW0[i*256 + c0 + 1];
            }
            e = fmaxf(e, 0.f); o = fmaxf(o, 0.f);
            uint32_t hi = pack_bf16x2(e, o);
            float eh = __uint_as_float(hi << 16);
            float oh = __uint_as_float(hi & 0xffff0000u);
            uint32_t lo = pack_bf16x2(e - eh, o - oh);
            *(uint32_t*)(rowh + c0*2) = hi;
            *(uint32_t*)(rowl + c0*2) = lo;
        }
    }
    __syncthreads();

    // ---- layers 1,2: mma; pair-scoped W-buffer protocol ----
    float acc[128];
    #pragma unroll
    for (int i = 0; i < 128; i++) acc[i] = 0.f;

    int arow   = wm*64 + (lane & 15);
    uint32_t aoff = (uint32_t)arow*528 + ((lane >> 4) & 1)*16;
    int nrow   = wn*64 + (lane & 7) + ((lane & 16) >> 1);
    uint32_t boff = (uint32_t)nrow*48 + ((lane >> 3) & 1)*16;

    #pragma unroll 1
    for (int layer = 0; layer < 2; layer++){
        #pragma unroll 1
        for (int c = 0; c < 16; c++){
            if (c < 15) __pipeline_wait_prior(1);
            else        __pipeline_wait_prior(0);
            PAIRBAR(barid);                 // pair's copies for chunk c all visible
            int buf = c & 1;
            uint32_t wbh = sbase + SW_OFF + buf*24576 + boff;
            uint32_t wbl = wbh + 12288;
            uint32_t bh[16], bl[16];
            #pragma unroll
            for (int ntp = 0; ntp < 4; ntp++){
                ldsm4(&bh[ntp*4], wbh + ntp*768);
                ldsm4(&bl[ntp*4], wbl + ntp*768);
            }
            uint32_t abase = sbase + aoff + (uint32_t)c*32;
            uint32_t ah[16], al[16];
            #pragma unroll
            for (int mf = 0; mf < 4; mf++){
                ldsm4(&ah[mf*4], abase + SA_HI + mf*8448);
                ldsm4(&al[mf*4], abase + SA_LO + mf*8448);
            }
            #pragma unroll
            for (int prod = 0; prod < 3; prod++){
                const uint32_t* A  = (prod == 1) ? al : ah;
                const uint32_t* Bf = (prod == 2) ? bl : bh;
                #pragma unroll
                for (int mf = 0; mf < 4; mf++){
                    #pragma unroll
                    for (int nt = 0; nt < 8; nt++){
                        mma_bf16(&acc[(mf*8 + nt)*4], &A[mf*4],
                                 &Bf[(nt >> 1)*4 + (nt & 1)*2]);
                    }
                }
            }
            if (c < 15){
                PAIRBAR(barid);             // pair done reading buf before refill
                if (c + 2 < 16) issue_wp(sm, layer, c + 2, c & 1, prow);
            }
        }
        // c == 15 fall-through: full sync (SA epilogue is cross-pair)
        __syncthreads();
        if (layer == 0){
            issue_wp(sm, 1, 0, 0, prow);
            issue_wp(sm, 1, 1, 1, prow);
        }
        const float* sb = layer ? sB2 : sB1;
        int erow = wm*64 + (lane >> 2);
        int ecol = wn*64 + (lane & 3)*2;
        #pragma unroll
        for (int mf = 0; mf < 4; mf++){
            #pragma unroll
            for (int nt = 0; nt < 8; nt++){
                float* C = &acc[(mf*8 + nt)*4];
                int col = ecol + nt*8;
                float bv0 = sb[col], bv1 = sb[col+1];
                #pragma unroll
                for (int half = 0; half < 2; half++){
                    int row = erow + mf*16 + half*8;
                    float v0 = fmaxf(C[half*2]   + bv0, 0.f);
                    float v1 = fmaxf(C[half*2+1] + bv1, 0.f);
                    uint32_t hi = pack_bf16x2(v0, v1);
                    float eh = __uint_as_float(hi << 16);
                    float oh = __uint_as_float(hi & 0xffff0000u);
                    uint32_t lo = pack_bf16x2(v0 - eh, v1 - oh);
                    *(uint32_t*)(sm + SA_HI + row*528 + col*2) = hi;
                    *(uint32_t*)(sm + SA_LO + row*528 + col*2) = lo;
                    C[half*2] = 0.f; C[half*2+1] = 0.f;
                }
            }
        }
        __syncthreads();
    }

    // ---- layer3: 256 -> 8 FFMA from SA ----
    {
        float a3[8];
        #pragma unroll
        for (int cc = 0; cc < 8; cc++) a3[cc] = 0.f;
        char* rowh = sm + SA_HI + r*528;
        char* rowl = sm + SA_LO + r*528;
        #pragma unroll 4
        for (int kk = 0; kk < 64; kk++){
            int k = h*128 + 2*kk;
            uint32_t wh = *(uint32_t*)(rowh + k*2);
            uint32_t wl = *(uint32_t*)(rowl + k*2);
            float v0 = __uint_as_float(wh << 16)          + __uint_as_float(wl << 16);
            float v1 = __uint_as_float(wh & 0xffff0000u)  + __uint_as_float(wl & 0xffff0000u);
            #pragma unroll
            for (int cc = 0; cc < 8; cc++){
                a3[cc] += v0*sW3[k*8 + cc] + v1*sW3[(k+1)*8 + cc];
            }
        }
        #pragma unroll
        for (int cc = 0; cc < 8; cc++)
            a3[cc] += __shfl_xor_sync(0xffffffffu, a3[cc], 1);
        if (h == 0){
            float* xo = g_xout + (size_t)grow*8;
            #pragma unroll
            for (int cc = 0; cc < 8; cc++) xo[cc] = a3[cc] + sB3[cc];
        }
    }
}

// ---------------- K4 + bisection(4 steps/barrier) + K5 fused (R8-proven) ----------------
__global__ void __launch_bounds__(256, 2) k_bis(){
    int tid = threadIdx.x;
    int bid = blockIdx.x;
    int gid = bid*256 + tid;        // 0..65535
    int lane = tid & 31, wid = tid >> 5;

    float A0[2],A1[2],A2[2],Cc0[2],Cc1[2],Cc2[2],Cc3[2];
    float Bar[2],Bai[2],Bbr[2],Bbi[2],Bcr[2],Bci[2],Bdr[2],Bdi[2];
    float uwr0[2],uwi0[2],uwr1[2],uwi1[2];
    float hc[2][8];

    #pragma unroll
    for (int q = 0; q < 2; q++){
        int p = gid + q*65536;
        float4 hc0 = g_Hc[2*p], hc1 = g_Hc[2*p+1];
        hc[q][0]=hc0.x; hc[q][1]=hc0.y; hc[q][2]=hc0.z; hc[q][3]=hc0.w;
        hc[q][4]=hc1.x; hc[q][5]=hc1.y; hc[q][6]=hc1.z; hc[q][7]=hc1.w;
        const float* x = g_xout + (size_t)p*8;
        float x0=x[0],x1=x[1],x2=x[2],x3=x[3],x4=x[4],x5=x[5],x6=x[6],x7=x[7];
        cf U0{x0,x2}, U1{x1,x3}, Wm0{x4,x6}, Wm1{x5,x7};
        float au0 = x0*x0 + x2*x2, au1 = x1*x1 + x3*x3;
        cf c0{Wm0.r*au0, Wm0.i*au0}, c1{Wm1.r*au1, Wm1.i*au1};
        cf h00{hc0.x,hc0.y}, h01{hc0.z,hc0.w}, h10{hc1.x,hc1.y}, h11{hc1.z,hc1.w};
        float n00 = cabs2(h00), n01 = cabs2(h01), n10 = cabs2(h10), n11 = cabs2(h11);
        cf Ba{c0.r*n00 + c1.r*n10, c0.i*n00 + c1.i*n10};
        cf Bd{c0.r*n01 + c1.r*n11, c0.i*n01 + c1.i*n11};
        cf Bb = cadd(cmul(c0, cmul(cconj(h00), h01)), cmul(c1, cmul(cconj(h10), h11)));
        cf Bc = cadd(cmul(c0, cmul(cconj(h01), h00)), cmul(c1, cmul(cconj(h11), h10)));
        cf uw0 = cmul(U0, Wm0), uw1 = cmul(U1, Wm1);
        cf g00 = cconj(h00), g01 = cconj(h01), g10 = cconj(h10), g11 = cconj(h11);
        cf p00 = csub(cmul(Bd,g00), cmul(Bb,g01));
        cf p01 = csub(cmul(Ba,g01), cmul(Bc,g00));
        cf p10 = csub(cmul(Bd,g10), cmul(Bb,g11));
        cf p11 = csub(cmul(Ba,g11), cmul(Bc,g10));
        float u0 = cabs2(uw0), u1 = cabs2(uw1);
        A0[q] = u0*(cabs2(p00)+cabs2(p01)) + u1*(cabs2(p10)+cabs2(p11));
        A1[q] = 2.f*( u0*(p00.r*g00.r + p00.i*g00.i + p01.r*g01.r + p01.i*g01.i)
                    + u1*(p10.r*g10.r + p10.i*g10.i + p11.r*g11.r + p11.i*g11.i) );
        A2[q] = u0*(cabs2(g00)+cabs2(g01)) + u1*(cabs2(g10)+cabs2(g11));
        cf T = cadd(Ba, Bd);
        cf D = csub(cmul(Ba,Bd), cmul(Bb,Bc));
        Cc0[q] = cabs2(D);
        Cc1[q] = 2.f*(T.r*D.r + T.i*D.i);
        Cc2[q] = T.r*T.r + T.i*T.i + 2.f*D.r;
        Cc3[q] = 2.f*T.r;
        Bar[q]=Ba.r; Bai[q]=Ba.i; Bbr[q]=Bb.r; Bbi[q]=Bb.i;
        Bcr[q]=Bc.r; Bci[q]=Bc.i; Bdr[q]=Bd.r; Bdi[q]=Bd.i;
        uwr0[q]=uw0.r; uwi0[q]=uw0.i; uwr1[q]=uw1.r; uwi1[q]=uw1.i;
    }

    __shared__ float swarp[8][16];
    __shared__ float spart[16][16];
    __shared__ float ssum[16];
    __shared__ int   slast;
    float lo = 0.f, hi = 10.f, mu = 5.f;

    #pragma unroll 1
    for (int round = 0; round < 5; round++){
        float L[16], Hh[16], m[16];
        L[1] = lo; Hh[1] = hi;
        #pragma unroll
        for (int i = 1; i < 8; i++){
            m[i] = 0.5f*(L[i] + Hh[i]);
            L[2*i] = L[i];  Hh[2*i] = m[i];
            L[2*i+1] = m[i]; Hh[2*i+1] = Hh[i];
        }
        #pragma unroll
        for (int i = 8; i < 16; i++) m[i] = 0.5f*(L[i] + Hh[i]);

        float v[15];
        #pragma unroll
        for (int node = 1; node <= 15; node++){
            float s = 2.0f*m[node];
            float a = 0.f;
            #pragma unroll
            for (int q = 0; q < 2; q++){
                float num = A0[q] + s*(A1[q] + s*A2[q]);
                float den = Cc0[q] + s*(Cc1[q] + s*(Cc2[q] + s*(Cc3[q] + s)));
                a += num/den;
            }
            v[node-1] = a;
        }
        #pragma unroll
        for (int j = 0; j < 15; j++){
            #pragma unroll
            for (int off = 16; off; off >>= 1)
                v[j] += __shfl_down_sync(0xffffffffu, v[j], off);
            if (lane == 0) swarp[wid][j] = v[j];
        }
        __syncthreads();
        if (tid < 15){
            float s = 0.f;
            #pragma unroll
            for (int w = 0; w < 8; w++) s += swarp[w][tid];
            g_part15[bid][tid] = s;
        }
        __threadfence();
        __syncthreads();
        if (tid == 0){
            unsigned old = atomicAdd(&g_ticket, 1u);
            slast = (old == (unsigned)(256*(round+1) - 1)) ? 1 : 0;
        }
        __syncthreads();
        if (slast){
            int j = tid & 15, chunk = tid >> 4;
            float sacc = 0.f;
            if (j < 15){
                volatile float* gp = &g_part15[0][0];
                int base = chunk*16;
                #pragma unroll
                for (int i = 0; i < 16; i++) sacc += gp[(base + i)*16 + j];
            }
            spart[chunk][j] = sacc;
            __syncthreads();
            if (tid < 15){
                float s = 0.f;
                #pragma unroll
                for (int cc = 0; cc < 16; cc++) s += spart[cc][tid];
                g_sum15[round][tid] = s;
            }
            __threadfence();
            __syncthreads();
            if (tid == 0){ g_dec5[round] = 1; __threadfence(); }
        }
        if (tid == 0){
            volatile int* dp = (volatile int*)&g_dec5[round];
            int d;
            do { d = *dp; } while (d == 0);
            __threadfence();
            volatile float* gs = &g_sum15[round][0];
            #pragma unroll
            for (int j = 0; j < 15; j++) ssum[j] = gs[j];
        }
        __syncthreads();
        float Lc = lo, Hc = hi;
        int node = 1;
        #pragma unroll
        for (int st = 0; st < 4; st++){
            float mm = 0.5f*(Lc + Hc);
            float S = ssum[node-1];
            mu = mm;
            if (S > 1.0f){ Lc = mm; node = 2*node + 1; }
            else         { Hc = mm; node = 2*node; }
        }
        lo = Lc; hi = Hc;
        __syncthreads();
    }

    // epilogue: final V + per-item power
    float s = 2.0f*mu;
    #pragma unroll
    for (int q = 0; q < 2; q++){
        int p = gid + q*65536;
        cf a{Bar[q] + s, Bai[q]}, b{Bbr[q], Bbi[q]}, c{Bcr[q], Bci[q]}, d{Bdr[q] + s, Bdi[q]};
        cf det = csub(cmul(a,d), cmul(b,c));
        float id = 1.0f/cabs2(det);
        cf idet{det.r*id, -det.i*id};
        cf g00{hc[q][0],-hc[q][1]}, g01{hc[q][2],-hc[q][3]};
        cf g10{hc[q][4],-hc[q][5]}, g11{hc[q][6],-hc[q][7]};
        cf y00 = cmul(csub(cmul(d,g00), cmul(b,g01)), idet);
        cf y01 = cmul(csub(cmul(a,g01), cmul(c,g00)), idet);
        cf y10 = cmul(csub(cmul(d,g10), cmul(b,g11)), idet);
        cf y11 = cmul(csub(cmul(a,g11), cmul(c,g10)), idet);
        cf uw0{uwr0[q],uwi0[q]}, uw1{uwr1[q],uwi1[q]};
        cf V00 = cmul(uw0,y00);
        cf V01 = cmul(uw1,y10);
        cf V10 = cmul(uw0,y01);
        cf V11 = cmul(uw1,y11);
        g_V[2*p]   = make_float4(V00.r,V00.i,V01.r,V01.i);
        g_V[2*p+1] = make_float4(V10.r,V10.i,V11.r,V11.i);
        float2 cr = g_cross[p & 4095];
        cf crs{cr.x, cr.y};
        cf t0 = cmul(crs, cmul(V00, cconj(V10)));
        cf t1 = cmul(crs, cmul(V01, cconj(V11)));
        g_Pw[p] = cabs2(V00)+cabs2(V10)+2.f*t0.r + cabs2(V01)+cabs2(V11)+2.f*t1.r;
    }
}

// ---------------- K6: output ----------------
__global__ void k6_out(float* __restrict__ out){
    int q = blockIdx.x*8 + (threadIdx.x >> 5);
    int l = threadIdx.x & 31;
    int n2 = q >> 12;
    int b3 = q & 4095;
    float sc = 1.41421356237f / sqrtf(g_Pw[b3*32 + n2]);
    float4 v0 = g_V[2*q], v1 = g_V[2*q+1];
    cf V00{v0.x,v0.y}, V01{v0.z,v0.w}, V10{v1.x,v1.y}, V11{v1.z,v1.w};
    const float4* frf = g_FRF + b3*64;
    float* baseR = out + (size_t)b3*8192 + n2*128;
    float* baseI = baseR + 4096;
    float4 fa = frf[2*l], fb = frf[2*l+1];
    cf fa0{fa.x,fa.y}, fa1{fa.z,fa.w}, fb0{fb.x,fb.y}, fb1{fb.z,fb.w};
    cf oa0 = cadd(cmul(fa0,V00), cmul(fa1,V10));
    cf oa1 = cadd(cmul(fa0,V01), cmul(fa1,V11));
    cf ob0 = cadd(cmul(fb0,V00), cmul(fb1,V10));
    cf ob1 = cadd(cmul(fb0,V01), cmul(fb1,V11));
    ((float4*)baseR)[l] = make_float4(sc*oa0.r, sc*oa1.r, sc*ob0.r, sc*ob1.r);
    ((float4*)baseI)[l] = make_float4(sc*oa0.i, sc*oa1.i, sc*ob0.i, sc*ob1.i);
}

// ---------------- launch ----------------
extern "C" void kernel_launch(void* const* d_in, const int* in_sizes, int n_in,
                              void* d_out, int out_size){
    const float* H  = (const float*)d_in[0];
    const float* W0 = (const float*)d_in[1]; const float* b0 = (const float*)d_in[2];
    const float* W1 = (const float*)d_in[3]; const float* b1 = (const float*)d_in[4];
    const float* W2 = (const float*)d_in[5]; const float* b2 = (const float*)d_in[6];
    const float* W3 = (const float*)d_in[7]; const float* b3 = (const float*)d_in[8];
    cudaFuncSetAttribute(k3_mma, cudaFuncAttributeMaxDynamicSharedMemorySize, K3_SMEM);

    k_wsplit<<<512,256>>>(W1, W2);
    k1_frf<<<BATCHN,64>>>(H);
    k2_hequ<<<16384,256>>>(H);
    k3_mma<<<1024,256,K3_SMEM>>>(W0, b0, b1, b2, W3, b3);
    k_bis<<<256,256>>>();
    k6_out<<<16384,256>>>((float*)d_out);
}

// round 15
// speedup vs baseline: 1.5519x; 1.0690x over previous
#include <cuda_runtime.h>
#include <cuda_bf16.h>
#include <cuda_pipeline.h>
#include <cstdint>

#define BATCHN 4096
#define NCC    32
#define NTT    64
#define NP     (BATCHN*NCC)   // 131072

// ---------------- scratch (static device globals; no allocation) ----------------
__device__ float4 g_FRF[BATCHN*NTT];
__device__ float4 g_colsum[BATCHN];
__device__ float2 g_cross[BATCHN];
__device__ float4 g_Hc[NP*2];
__device__ float  g_xin[NP*8];
__device__ float  g_xout[NP*8];
__device__ float4 g_V[NP*2];
__device__ float  g_Pw[NP];
__device__ float  g_part15[256][16];
__device__ float  g_sum15[5][16];
__device__ int    g_dec5[5];
__device__ unsigned g_ticket;
// bf16 hi/lo split weights, chunk-major layout: [kchunk(16)][n(256)][kk(16)]
__device__ __nv_bfloat16 g_W1hi[65536], g_W1lo[65536], g_W2hi[65536], g_W2lo[65536];

// ---------------- complex helpers ----------------
struct cf { float r, i; };
__device__ __forceinline__ cf cmul(cf a, cf b){ return {a.r*b.r - a.i*b.i, a.r*b.i + a.i*b.r}; }
__device__ __forceinline__ cf cadd(cf a, cf b){ return {a.r+b.r, a.i+b.i}; }
__device__ __forceinline__ cf csub(cf a, cf b){ return {a.r-b.r, a.i-b.i}; }
__device__ __forceinline__ cf cconj(cf a){ return {a.r, -a.i}; }
__device__ __forceinline__ float cabs2(cf a){ return a.r*a.r + a.i*a.i; }

// ---------------- warp mma helpers (plain sm_100 PTX) ----------------
__device__ __forceinline__ uint32_t smem_u32(const void* p){
    uint32_t a;
    asm("{ .reg .u64 t; cvta.to.shared.u64 t, %1; cvt.u32.u64 %0, t; }" : "=r"(a) : "l"(p));
    return a;
}
__device__ __forceinline__ void ldsm4(uint32_t* r, uint32_t addr){
    asm volatile("ldmatrix.sync.aligned.m8n8.x4.shared.b16 {%0,%1,%2,%3},[%4];"
                 : "=r"(r[0]),"=r"(r[1]),"=r"(r[2]),"=r"(r[3]) : "r"(addr));
}
__device__ __forceinline__ void mma_bf16(float* c, const uint32_t* a, const uint32_t* b){
    asm volatile("mma.sync.aligned.m16n8k16.row.col.f32.bf16.bf16.f32 "
                 "{%0,%1,%2,%3},{%4,%5,%6,%7},{%8,%9},{%0,%1,%2,%3};"
                 : "+f"(c[0]),"+f"(c[1]),"+f"(c[2]),"+f"(c[3])
                 : "r"(a[0]),"r"(a[1]),"r"(a[2]),"r"(a[3]), "r"(b[0]),"r"(b[1]));
}
__device__ __forceinline__ uint32_t pack_bf16x2(float even, float odd){
    uint32_t r;
    asm("cvt.rn.bf16x2.f32 %0, %1, %2;" : "=r"(r) : "f"(odd), "f"(even));  // low=even, high=odd
    return r;
}
#define PAIRBAR(id) asm volatile("bar.sync %0, 64;" :: "r"(id) : "memory")

// ---------------- K1: F_RF + column sums + cross ----------------
__global__ void k1_frf(const float* __restrict__ H){
    int b = blockIdx.x;
    int t = threadIdx.x;     // 64 threads
    const float* r0 = H + ((size_t)(b*2+0)*32 + 16)*128;
    const float* r1 = H + ((size_t)(b*2+1)*32 + 16)*128;
    float h0a = r0[0], h0b = r1[0];
    float hra = r0[t], hrb = r1[t];
    float inva = 1.0f/(8.0f*sqrtf(hra*hra + h0a*h0a));
    float invb = 1.0f/(8.0f*sqrtf(hrb*hrb + h0b*h0b));
    float f0r =  hra*inva, f0i = -h0a*inva;
    float f1r =  hrb*invb, f1i = -h0b*invb;
    g_FRF[b*64+t] = make_float4(f0r, f0i, f1r, f1i);
    float cr = f0r*f1r + f0i*f1i;
    float ci = f0i*f1r - f0r*f1i;
    __shared__ float s[6*64];
    s[0*64+t]=f0r; s[1*64+t]=f0i; s[2*64+t]=f1r; s[3*64+t]=f1i; s[4*64+t]=cr; s[5*64+t]=ci;
    __syncthreads();
    for (int off=32; off>=1; off>>=1){
        if (t < off){
            #pragma unroll
            for (int i=0;i<6;i++) s[i*64+t] += s[i*64+t+off];
        }
        __syncthreads();
    }
    if (t==0){
        g_colsum[b] = make_float4(s[0], s[64], s[128], s[192]);
        g_cross[b]  = make_float2(s[256], s[320]);
    }
}

// ---------------- K2: H_equ (normalized) + MLP input (smem reduction, R12-proven) ----------------
__global__ void k2_hequ(const float* __restrict__ H){
    __shared__ float4 sfrf[64];
    __shared__ float4 scs;
    __shared__ float sred[8*288];
    __shared__ float ssum[64];
    int b2 = blockIdx.x >> 2;
    int g  = blockIdx.x & 3;
    int tid = threadIdx.x;
    if (tid < 64) sfrf[tid] = g_FRF[b2*64 + tid];
    if (tid == 64) scs = g_colsum[b2];
    __syncthreads();
    int w = tid >> 5, l = tid & 31;
    int p = (g*8 + w)*4096 + b2;
    const float* r0 = H + (size_t)(2*p)*128;
    const float* r1 = r0 + 128;
    float a00r=0,a00i=0,a01r=0,a01i=0,a10r=0,a10i=0,a11r=0,a11i=0;
    #pragma unroll
    for (int k=0;k<2;k++){
        int tt = l + k*32;
        float4 f = sfrf[tt];
        float x0 = r0[tt], x1 = r1[tt];
        a00r += x0*f.x; a00i += x0*f.y; a01r += x0*f.z; a01i += x0*f.w;
        a10r += x1*f.x; a10i += x1*f.y; a11r += x1*f.z; a11i += x1*f.w;
    }
    float* dst = &sred[w*288 + l*9];
    dst[0]=a00r; dst[1]=a00i; dst[2]=a01r; dst[3]=a01i;
    dst[4]=a10r; dst[5]=a10i; dst[6]=a11r; dst[7]=a11i;
    __syncthreads();
    if (tid < 64){
        int w2 = tid >> 3, v = tid & 7;
        float s = 0.f;
        #pragma unroll
        for (int ll = 0; ll < 32; ll++) s += sred[w2*288 + ll*9 + v];
        ssum[tid] = s;
    }
    __syncthreads();
    if (tid < 8){
        int p2 = (g*8 + tid)*4096 + b2;
        const float* q0 = H + (size_t)(2*p2)*128;
        float h00 = q0[0], h01 = q0[128];
        float b00r=ssum[tid*8+0], b00i=ssum[tid*8+1], b01r=ssum[tid*8+2], b01i=ssum[tid*8+3];
        float b10r=ssum[tid*8+4], b10i=ssum[tid*8+5], b11r=ssum[tid*8+6], b11i=ssum[tid*8+7];
        float4 cs = scs;
        float m00r = b00r - h00*cs.y, m00i = b00i + h00*cs.x;
        float m01r = b01r - h00*cs.w, m01i = b01i + h00*cs.z;
        float m10r = b10r - h01*cs.y, m10i = b10i + h01*cs.x;
        float m11r = b11r - h01*cs.w, m11i = b11i + h01*cs.z;
        float pw = m00r*m00r+m00i*m00i+m01r*m01r+m01i*m01i
                 + m10r*m10r+m10i*m10i+m11r*m11r+m11i*m11i;
        float inv = 1.0f/sqrtf(pw);
        m00r*=inv; m00i*=inv; m01r*=inv; m01i*=inv;
        m10r*=inv; m10i*=inv; m11r*=inv; m11i*=inv;
        g_Hc[2*p2]   = make_float4(m00r,m00i,m01r,m01i);
        g_Hc[2*p2+1] = make_float4(m10r,m10i,m11r,m11i);
        float* xo = g_xin + (size_t)p2*8;
        xo[0]=m00r; xo[1]=m01r; xo[2]=m10r; xo[3]=m11r;
        xo[4]=m00i; xo[5]=m01i; xo[6]=m10i; xo[7]=m11i;
    }
}

// ---------------- weight split (+ bisection state init) ----------------
__global__ void k_wsplit(const float* __restrict__ W1, const float* __restrict__ W2){
    if (blockIdx.x == 0 && threadIdx.x == 0){
        g_ticket = 0u;
        for (int i = 0; i < 5; i++) g_dec5[i] = 0;
    }
    int idx = blockIdx.x*256 + threadIdx.x;     // 0..131071
    int layer = idx >> 16;
    int e = idx & 65535;
    int n = e & 255, k = e >> 8;
    float v = (layer ? W2 : W1)[k*256 + n];
    __nv_bfloat16 h = __float2bfloat16(v);
    __nv_bfloat16 l = __float2bfloat16(v - __bfloat162float(h));
    int pos = (k >> 4)*4096 + n*16 + (k & 15);
    if (layer){ g_W2hi[pos] = h; g_W2lo[pos] = l; }
    else      { g_W1hi[pos] = h; g_W1lo[pos] = l; }
}

// ---------------- K3: mma.sync bf16x3 MLP (256 thr, 3-buf swizzled, 1 pair-bar/chunk) ----------------
#define SA_HI   0          // 128 rows x 264 halves (stride 528B) = 67584
#define SA_LO   67584
#define SW_OFF  135168     // 3 buf x (hi 8192 + lo 8192) = 49152  (same region as before)
#define SW0_OFF 184320
#define SW3_OFF 192512
#define SB0_OFF 200704
#define SB1_OFF 201728
#define SB2_OFF 202752
#define SB3_OFF 203776
#define K3_SMEM 203904

// 32B/row swizzled buffer: unit h8 of row n at n*32 + ((h8 ^ ((n>>2)&1))*16)
__device__ __forceinline__ void issue_wp3(char* sm, int gch, int n){
    int layer = gch >> 4, c = gch & 15, buf = gch % 3;
    const __nv_bfloat16* gh = layer ? g_W2hi : g_W1hi;
    const __nv_bfloat16* gl = layer ? g_W2lo : g_W1lo;
    int sw = ((n >> 2) & 1)*16;
    char* dhi = sm + SW_OFF + buf*16384 + n*32;
    char* dlo = dhi + 8192;
    const __nv_bfloat16* srch = gh + c*4096 + n*16;
    const __nv_bfloat16* srcl = gl + c*4096 + n*16;
    __pipeline_memcpy_async(dhi + sw,        srch,     16);
    __pipeline_memcpy_async(dhi + (16^sw),   srch + 8, 16);
    __pipeline_memcpy_async(dlo + sw,        srcl,     16);
    __pipeline_memcpy_async(dlo + (16^sw),   srcl + 8, 16);
    __pipeline_commit();
}

__global__ void __launch_bounds__(256, 1) k3_mma(
        const float* __restrict__ W0, const float* __restrict__ b0v,
        const float* __restrict__ b1v, const float* __restrict__ b2v,
        const float* __restrict__ W3, const float* __restrict__ b3v){
    extern __shared__ char sm[];
    uint32_t sbase = smem_u32(sm);
    int tid  = threadIdx.x;
    int wid  = tid >> 5, lane = tid & 31;
    int wm   = wid >> 2;        // rowgroup 0..1 (64 rows)
    int wn   = wid & 3;         // ngroup  0..3 (64 cols)
    int prow = wn*64 + wm*32 + lane;   // this thread's B-row (pair region)
    int barid = 1 + wn;

    issue_wp3(sm, 0, prow);
    issue_wp3(sm, 1, prow);

    float* sW0 = (float*)(sm + SW0_OFF);
    float* sW3 = (float*)(sm + SW3_OFF);
    float* sB0 = (float*)(sm + SB0_OFF);
    float* sB1 = (float*)(sm + SB1_OFF);
    float* sB2 = (float*)(sm + SB2_OFF);
    float* sB3 = (float*)(sm + SB3_OFF);
    #pragma unroll
    for (int i = tid; i < 2048; i += 256){ sW0[i] = W0[i]; sW3[i] = W3[i]; }
    if (tid < 256){ sB0[tid] = b0v[tid]; sB1[tid] = b1v[tid]; sB2[tid] = b2v[tid]; }
    if (tid < 8) sB3[tid] = b3v[tid];

    // ---- layer0: 8 -> 256 FFMA, split, write SA ----
    int r = tid >> 1, h = tid & 1;
    int grow = blockIdx.x*128 + r;
    float xr[8];
    {
        float4 a = *(const float4*)(g_xin + (size_t)grow*8);
        float4 b = *(const float4*)(g_xin + (size_t)grow*8 + 4);
        xr[0]=a.x; xr[1]=a.y; xr[2]=a.z; xr[3]=a.w;
        xr[4]=b.x; xr[5]=b.y; xr[6]=b.z; xr[7]=b.w;
    }
    __syncthreads();
    {
        char* rowh = sm + SA_HI + r*528;
        char* rowl = sm + SA_LO + r*528;
        #pragma unroll 4
        for (int cc = 0; cc < 64; cc++){
            int c0 = h*128 + 2*cc;
            float e = sB0[c0], o = sB0[c0+1];
            #pragma unroll
            for (int i = 0; i < 8; i++){
                e += xr[i]*sW0[i*256 + c0];
                o += xr[i]*sW0[i*256 + c0 + 1];
            }
            e = fmaxf(e, 0.f); o = fmaxf(o, 0.f);
            uint32_t hi = pack_bf16x2(e, o);
            float eh = __uint_as_float(hi << 16);
            float oh = __uint_as_float(hi & 0xffff0000u);
            uint32_t lo = pack_bf16x2(e - eh, o - oh);
            *(uint32_t*)(rowh + c0*2) = hi;
            *(uint32_t*)(rowl + c0*2) = lo;
        }
    }
    __syncthreads();

    // ---- layers 1,2: mma over 32 global chunks; 3-buf, one pair-bar per chunk ----
    float acc[128];
    #pragma unroll
    for (int i = 0; i < 128; i++) acc[i] = 0.f;

    int arow   = wm*64 + (lane & 15);
    uint32_t aoff = (uint32_t)arow*528 + ((lane >> 4) & 1)*16;
    int nrow   = wn*64 + (lane & 7) + ((lane & 16) >> 1);
    uint32_t boff = (uint32_t)nrow*32 + (uint32_t)((((lane >> 3) & 1) ^ ((nrow >> 2) & 1))*16);

    #pragma unroll 1
    for (int gch = 0; gch < 32; gch++){
        if (gch < 31) __pipeline_wait_prior(1);
        else          __pipeline_wait_prior(0);
        PAIRBAR(barid);           // chunk gch visible; both warps past gch-1 -> buf (gch+2)%3 free
        if (gch + 2 < 32) issue_wp3(sm, gch + 2, prow);
        int buf = gch % 3;
        int c   = gch & 15;
        uint32_t wbh = sbase + SW_OFF + (uint32_t)buf*16384 + boff;
        uint32_t wbl = wbh + 8192;
        uint32_t bh[16], bl[16];
        #pragma unroll
        for (int ntp = 0; ntp < 4; ntp++){
            ldsm4(&bh[ntp*4], wbh + ntp*512);
            ldsm4(&bl[ntp*4], wbl + ntp*512);
        }
        uint32_t abase = sbase + aoff + (uint32_t)c*32;
        uint32_t ah[16], al[16];
        #pragma unroll
        for (int mf = 0; mf < 4; mf++){
            ldsm4(&ah[mf*4], abase + SA_HI + mf*8448);
            ldsm4(&al[mf*4], abase + SA_LO + mf*8448);
        }
        #pragma unroll
        for (int prod = 0; prod < 3; prod++){
            const uint32_t* A  = (prod == 1) ? al : ah;
            const uint32_t* Bf = (prod == 2) ? bl : bh;
            #pragma unroll
            for (int mf = 0; mf < 4; mf++){
                #pragma unroll
                for (int nt = 0; nt < 8; nt++){
                    mma_bf16(&acc[(mf*8 + nt)*4], &A[mf*4],
                             &Bf[(nt >> 1)*4 + (nt & 1)*2]);
                }
            }
        }
        if (c == 15){
            __syncthreads();   // all warps done reading SA for this layer
            const float* sb = (gch >> 4) ? sB2 : sB1;
            int erow = wm*64 + (lane >> 2);
            int ecol = wn*64 + (lane & 3)*2;
            #pragma unroll
            for (int mf = 0; mf < 4; mf++){
                #pragma unroll
                for (int nt = 0; nt < 8; nt++){
                    float* C = &acc[(mf*8 + nt)*4];
                    int col = ecol + nt*8;
                    float bv0 = sb[col], bv1 = sb[col+1];
                    #pragma unroll
                    for (int half = 0; half < 2; half++){
                        int row = erow + mf*16 + half*8;
                        float v0 = fmaxf(C[half*2]   + bv0, 0.f);
                        float v1 = fmaxf(C[half*2+1] + bv1, 0.f);
                        uint32_t hi = pack_bf16x2(v0, v1);
                        float eh = __uint_as_float(hi << 16);
                        float oh = __uint_as_float(hi & 0xffff0000u);
                        uint32_t lo = pack_bf16x2(v0 - eh, v1 - oh);
                        *(uint32_t*)(sm + SA_HI + row*528 + col*2) = hi;
                        *(uint32_t*)(sm + SA_LO + row*528 + col*2) = lo;
                        C[half*2] = 0.f; C[half*2+1] = 0.f;
                    }
                }
            }
            __syncthreads();   // epilogue SA writes complete before next layer's A-ldsm
        }
    }

    // ---- layer3: 256 -> 8 FFMA from SA ----
    {
        float a3[8];
        #pragma unroll
        for (int cc = 0; cc < 8; cc++) a3[cc] = 0.f;
        char* rowh = sm + SA_HI + r*528;
        char* rowl = sm + SA_LO + r*528;
        #pragma unroll 4
        for (int kk = 0; kk < 64; kk++){
            int k = h*128 + 2*kk;
            uint32_t wh = *(uint32_t*)(rowh + k*2);
            uint32_t wl = *(uint32_t*)(rowl + k*2);
            float v0 = __uint_as_float(wh << 16)          + __uint_as_float(wl << 16);
            float v1 = __uint_as_float(wh & 0xffff0000u)  + __uint_as_float(wl & 0xffff0000u);
            #pragma unroll
            for (int cc = 0; cc < 8; cc++){
                a3[cc] += v0*sW3[k*8 + cc] + v1*sW3[(k+1)*8 + cc];
            }
        }
        #pragma unroll
        for (int cc = 0; cc < 8; cc++)
            a3[cc] += __shfl_xor_sync(0xffffffffu, a3[cc], 1);
        if (h == 0){
            float* xo = g_xout + (size_t)grow*8;
            #pragma unroll
            for (int cc = 0; cc < 8; cc++) xo[cc] = a3[cc] + sB3[cc];
        }
    }
}

// ---------------- K4 + bisection(4 steps/barrier) + K5 fused (R8-proven) ----------------
__global__ void __launch_bounds__(256, 2) k_bis(){
    int tid = threadIdx.x;
    int bid = blockIdx.x;
    int gid = bid*256 + tid;        // 0..65535
    int lane = tid & 31, wid = tid >> 5;

    float A0[2],A1[2],A2[2],Cc0[2],Cc1[2],Cc2[2],Cc3[2];
    float Bar[2],Bai[2],Bbr[2],Bbi[2],Bcr[2],Bci[2],Bdr[2],Bdi[2];
    float uwr0[2],uwi0[2],uwr1[2],uwi1[2];
    float hc[2][8];

    #pragma unroll
    for (int q = 0; q < 2; q++){
        int p = gid + q*65536;
        float4 hc0 = g_Hc[2*p], hc1 = g_Hc[2*p+1];
        hc[q][0]=hc0.x; hc[q][1]=hc0.y; hc[q][2]=hc0.z; hc[q][3]=hc0.w;
        hc[q][4]=hc1.x; hc[q][5]=hc1.y; hc[q][6]=hc1.z; hc[q][7]=hc1.w;
        const float* x = g_xout + (size_t)p*8;
        float x0=x[0],x1=x[1],x2=x[2],x3=x[3],x4=x[4],x5=x[5],x6=x[6],x7=x[7];
        cf U0{x0,x2}, U1{x1,x3}, Wm0{x4,x6}, Wm1{x5,x7};
        float au0 = x0*x0 + x2*x2, au1 = x1*x1 + x3*x3;
        cf c0{Wm0.r*au0, Wm0.i*au0}, c1{Wm1.r*au1, Wm1.i*au1};
        cf h00{hc0.x,hc0.y}, h01{hc0.z,hc0.w}, h10{hc1.x,hc1.y}, h11{hc1.z,hc1.w};
        float n00 = cabs2(h00), n01 = cabs2(h01), n10 = cabs2(h10), n11 = cabs2(h11);
        cf Ba{c0.r*n00 + c1.r*n10, c0.i*n00 + c1.i*n10};
        cf Bd{c0.r*n01 + c1.r*n11, c0.i*n01 + c1.i*n11};
        cf Bb = cadd(cmul(c0, cmul(cconj(h00), h01)), cmul(c1, cmul(cconj(h10), h11)));
        cf Bc = cadd(cmul(c0, cmul(cconj(h01), h00)), cmul(c1, cmul(cconj(h11), h10)));
        cf uw0 = cmul(U0, Wm0), uw1 = cmul(U1, Wm1);
        cf g00 = cconj(h00), g01 = cconj(h01), g10 = cconj(h10), g11 = cconj(h11);
        cf p00 = csub(cmul(Bd,g00), cmul(Bb,g01));
        cf p01 = csub(cmul(Ba,g01), cmul(Bc,g00));
        cf p10 = csub(cmul(Bd,g10), cmul(Bb,g11));
        cf p11 = csub(cmul(Ba,g11), cmul(Bc,g10));
        float u0 = cabs2(uw0), u1 = cabs2(uw1);
        A0[q] = u0*(cabs2(p00)+cabs2(p01)) + u1*(cabs2(p10)+cabs2(p11));
        A1[q] = 2.f*( u0*(p00.r*g00.r + p00.i*g00.i + p01.r*g01.r + p01.i*g01.i)
                    + u1*(p10.r*g10.r + p10.i*g10.i + p11.r*g11.r + p11.i*g11.i) );
        A2[q] = u0*(cabs2(g00)+cabs2(g01)) + u1*(cabs2(g10)+cabs2(g11));
        cf T = cadd(Ba, Bd);
        cf D = csub(cmul(Ba,Bd), cmul(Bb,Bc));
        Cc0[q] = cabs2(D);
        Cc1[q] = 2.f*(T.r*D.r + T.i*D.i);
        Cc2[q] = T.r*T.r + T.i*T.i + 2.f*D.r;
        Cc3[q] = 2.f*T.r;
        Bar[q]=Ba.r; Bai[q]=Ba.i; Bbr[q]=Bb.r; Bbi[q]=Bb.i;
        Bcr[q]=Bc.r; Bci[q]=Bc.i; Bdr[q]=Bd.r; Bdi[q]=Bd.i;
        uwr0[q]=uw0.r; uwi0[q]=uw0.i; uwr1[q]=uw1.r; uwi1[q]=uw1.i;
    }

    __shared__ float swarp[8][16];
    __shared__ float spart[16][16];
    __shared__ float ssum[16];
    __shared__ int   slast;
    float lo = 0.f, hi = 10.f, mu = 5.f;

    #pragma unroll 1
    for (int round = 0; round < 5; round++){
        float L[16], Hh[16], m[16];
        L[1] = lo; Hh[1] = hi;
        #pragma unroll
        for (int i = 1; i < 8; i++){
            m[i] = 0.5f*(L[i] + Hh[i]);
            L[2*i] = L[i];  Hh[2*i] = m[i];
            L[2*i+1] = m[i]; Hh[2*i+1] = Hh[i];
        }
        #pragma unroll
        for (int i = 8; i < 16; i++) m[i] = 0.5f*(L[i] + Hh[i]);

        float v[15];
        #pragma unroll
        for (int node = 1; node <= 15; node++){
            float s = 2.0f*m[node];
            float a = 0.f;
            #pragma unroll
            for (int q = 0; q < 2; q++){
                float num = A0[q] + s*(A1[q] + s*A2[q]);
                float den = Cc0[q] + s*(Cc1[q] + s*(Cc2[q] + s*(Cc3[q] + s)));
                a += num/den;
            }
            v[node-1] = a;
        }
        #pragma unroll
        for (int j = 0; j < 15; j++){
            #pragma unroll
            for (int off = 16; off; off >>= 1)
                v[j] += __shfl_down_sync(0xffffffffu, v[j], off);
            if (lane == 0) swarp[wid][j] = v[j];
        }
        __syncthreads();
        if (tid < 15){
            float s = 0.f;
            #pragma unroll
            for (int w = 0; w < 8; w++) s += swarp[w][tid];
            g_part15[bid][tid] = s;
        }
        __threadfence();
        __syncthreads();
        if (tid == 0){
            unsigned old = atomicAdd(&g_ticket, 1u);
            slast = (old == (unsigned)(256*(round+1) - 1)) ? 1 : 0;
        }
        __syncthreads();
        if (slast){
            int j = tid & 15, chunk = tid >> 4;
            float sacc = 0.f;
            if (j < 15){
                volatile float* gp = &g_part15[0][0];
                int base = chunk*16;
                #pragma unroll
                for (int i = 0; i < 16; i++) sacc += gp[(base + i)*16 + j];
            }
            spart[chunk][j] = sacc;
            __syncthreads();
            if (tid < 15){
                float s = 0.f;
                #pragma unroll
                for (int cc = 0; cc < 16; cc++) s += spart[cc][tid];
                g_sum15[round][tid] = s;
            }
            __threadfence();
            __syncthreads();
            if (tid == 0){ g_dec5[round] = 1; __threadfence(); }
        }
        if (tid == 0){
            volatile int* dp = (volatile int*)&g_dec5[round];
            int d;
            do { d = *dp; } while (d == 0);
            __threadfence();
            volatile float* gs = &g_sum15[round][0];
            #pragma unroll
            for (int j = 0; j < 15; j++) ssum[j] = gs[j];
        }
        __syncthreads();
        float Lc = lo, Hc = hi;
        int node = 1;
        #pragma unroll
        for (int st = 0; st < 4; st++){
            float mm = 0.5f*(Lc + Hc);
            float S = ssum[node-1];
            mu = mm;
            if (S > 1.0f){ Lc = mm; node = 2*node + 1; }
            else         { Hc = mm; node = 2*node; }
        }
        lo = Lc; hi = Hc;
        __syncthreads();
    }

    // epilogue: final V + per-item power
    float s = 2.0f*mu;
    #pragma unroll
    for (int q = 0; q < 2; q++){
        int p = gid + q*65536;
        cf a{Bar[q] + s, Bai[q]}, b{Bbr[q], Bbi[q]}, c{Bcr[q], Bci[q]}, d{Bdr[q] + s, Bdi[q]};
        cf det = csub(cmul(a,d), cmul(b,c));
        float id = 1.0f/cabs2(det);
        cf idet{det.r*id, -det.i*id};
        cf g00{hc[q][0],-hc[q][1]}, g01{hc[q][2],-hc[q][3]};
        cf g10{hc[q][4],-hc[q][5]}, g11{hc[q][6],-hc[q][7]};
        cf y00 = cmul(csub(cmul(d,g00), cmul(b,g01)), idet);
        cf y01 = cmul(csub(cmul(a,g01), cmul(c,g00)), idet);
        cf y10 = cmul(csub(cmul(d,g10), cmul(b,g11)), idet);
        cf y11 = cmul(csub(cmul(a,g11), cmul(c,g10)), idet);
        cf uw0{uwr0[q],uwi0[q]}, uw1{uwr1[q],uwi1[q]};
        cf V00 = cmul(uw0,y00);
        cf V01 = cmul(uw1,y10);
        cf V10 = cmul(uw0,y01);
        cf V11 = cmul(uw1,y11);
        g_V[2*p]   = make_float4(V00.r,V00.i,V01.r,V01.i);
        g_V[2*p+1] = make_float4(V10.r,V10.i,V11.r,V11.i);
        float2 cr = g_cross[p & 4095];
        cf crs{cr.x, cr.y};
        cf t0 = cmul(crs, cmul(V00, cconj(V10)));
        cf t1 = cmul(crs, cmul(V01, cconj(V11)));
        g_Pw[p] = cabs2(V00)+cabs2(V10)+2.f*t0.r + cabs2(V01)+cabs2(V11)+2.f*t1.r;
    }
}

// ---------------- K6: output ----------------
__global__ void k6_out(float* __restrict__ out){
    int q = blockIdx.x*8 + (threadIdx.x >> 5);
    int l = threadIdx.x & 31;
    int n2 = q >> 12;
    int b3 = q & 4095;
    float sc = 1.41421356237f / sqrtf(g_Pw[b3*32 + n2]);
    float4 v0 = g_V[2*q], v1 = g_V[2*q+1];
    cf V00{v0.x,v0.y}, V01{v0.z,v0.w}, V10{v1.x,v1.y}, V11{v1.z,v1.w};
    const float4* frf = g_FRF + b3*64;
    float* baseR = out + (size_t)b3*8192 + n2*128;
    float* baseI = baseR + 4096;
    float4 fa = frf[2*l], fb = frf[2*l+1];
    cf fa0{fa.x,fa.y}, fa1{fa.z,fa.w}, fb0{fb.x,fb.y}, fb1{fb.z,fb.w};
    cf oa0 = cadd(cmul(fa0,V00), cmul(fa1,V10));
    cf oa1 = cadd(cmul(fa0,V01), cmul(fa1,V11));
    cf ob0 = cadd(cmul(fb0,V00), cmul(fb1,V10));
    cf ob1 = cadd(cmul(fb0,V01), cmul(fb1,V11));
    ((float4*)baseR)[l] = make_float4(sc*oa0.r, sc*oa1.r, sc*ob0.r, sc*ob1.r);
    ((float4*)baseI)[l] = make_float4(sc*oa0.i, sc*oa1.i, sc*ob0.i, sc*ob1.i);
}

// ---------------- launch ----------------
extern "C" void kernel_launch(void* const* d_in, const int* in_sizes, int n_in,
                              void* d_out, int out_size){
    const float* H  = (const float*)d_in[0];
    const float* W0 = (const float*)d_in[1]; const float* b0 = (const float*)d_in[2];
    const float* W1 = (const float*)d_in[3]; const float* b1 = (const float*)d_in[4];
    const float* W2 = (const float*)d_in[5]; const float* b2 = (const float*)d_in[6];
    const float* W3 = (const float*)d_in[7]; const float* b3 = (const float*)d_in[8];
    cudaFuncSetAttribute(k3_mma, cudaFuncAttributeMaxDynamicSharedMemorySize, K3_SMEM);

    k_wsplit<<<512,256>>>(W1, W2);
    k1_frf<<<BATCHN,64>>>(H);
    k2_hequ<<<16384,256>>>(H);
    k3_mma<<<1024,256,K3_SMEM>>>(W0, b0, b1, b2, W3, b3);
    k_bis<<<256,256>>>();
    k6_out<<<16384,256>>>((float*)d_out);
}

// round 16
// speedup vs baseline: 1.5578x; 1.0038x over previous
#include <cuda_runtime.h>
#include <cuda_bf16.h>
#include <cuda_pipeline.h>
#include <cstdint>

#define BATCHN 4096
#define NCC    32
#define NTT    64
#define NP     (BATCHN*NCC)   // 131072

// ---------------- scratch (static device globals; no allocation) ----------------
__device__ float4 g_FRF[BATCHN*NTT];
__device__ float4 g_colsum[BATCHN];
__device__ float2 g_cross[BATCHN];
__device__ float4 g_Hc[NP*2];
__device__ float  g_xin[NP*8];
__device__ float  g_xout[NP*8];
__device__ float4 g_V[NP*2];
__device__ float  g_Pw[NP];
__device__ float  g_part15[256][16];
__device__ float  g_sum15[5][16];
__device__ int    g_dec5[5];
__device__ unsigned g_ticket;
// bf16 hi/lo split weights, chunk-major layout: [kchunk(16)][n(256)][kk(16)]
__device__ __nv_bfloat16 g_W1hi[65536], g_W1lo[65536], g_W2hi[65536], g_W2lo[65536];

// ---------------- complex helpers ----------------
struct cf { float r, i; };
__device__ __forceinline__ cf cmul(cf a, cf b){ return {a.r*b.r - a.i*b.i, a.r*b.i + a.i*b.r}; }
__device__ __forceinline__ cf cadd(cf a, cf b){ return {a.r+b.r, a.i+b.i}; }
__device__ __forceinline__ cf csub(cf a, cf b){ return {a.r-b.r, a.i-b.i}; }
__device__ __forceinline__ cf cconj(cf a){ return {a.r, -a.i}; }
__device__ __forceinline__ float cabs2(cf a){ return a.r*a.r + a.i*a.i; }

// ---------------- warp mma helpers (plain sm_100 PTX) ----------------
__device__ __forceinline__ uint32_t smem_u32(const void* p){
    uint32_t a;
    asm("{ .reg .u64 t; cvta.to.shared.u64 t, %1; cvt.u32.u64 %0, t; }" : "=r"(a) : "l"(p));
    return a;
}
__device__ __forceinline__ void ldsm4(uint32_t* r, uint32_t addr){
    asm volatile("ldmatrix.sync.aligned.m8n8.x4.shared.b16 {%0,%1,%2,%3},[%4];"
                 : "=r"(r[0]),"=r"(r[1]),"=r"(r[2]),"=r"(r[3]) : "r"(addr));
}
__device__ __forceinline__ void mma_bf16(float* c, const uint32_t* a, const uint32_t* b){
    asm volatile("mma.sync.aligned.m16n8k16.row.col.f32.bf16.bf16.f32 "
                 "{%0,%1,%2,%3},{%4,%5,%6,%7},{%8,%9},{%0,%1,%2,%3};"
                 : "+f"(c[0]),"+f"(c[1]),"+f"(c[2]),"+f"(c[3])
                 : "r"(a[0]),"r"(a[1]),"r"(a[2]),"r"(a[3]), "r"(b[0]),"r"(b[1]));
}
__device__ __forceinline__ uint32_t pack_bf16x2(float even, float odd){
    uint32_t r;
    asm("cvt.rn.bf16x2.f32 %0, %1, %2;" : "=r"(r) : "f"(odd), "f"(even));  // low=even, high=odd
    return r;
}
#define PAIRBAR(id) asm volatile("bar.sync %0, 64;" :: "r"(id) : "memory")

// ---------------- K1: F_RF + column sums + cross ----------------
__global__ void k1_frf(const float* __restrict__ H){
    int b = blockIdx.x;
    int t = threadIdx.x;     // 64 threads
    const float* r0 = H + ((size_t)(b*2+0)*32 + 16)*128;
    const float* r1 = H + ((size_t)(b*2+1)*32 + 16)*128;
    float h0a = r0[0], h0b = r1[0];
    float hra = r0[t], hrb = r1[t];
    float inva = 1.0f/(8.0f*sqrtf(hra*hra + h0a*h0a));
    float invb = 1.0f/(8.0f*sqrtf(hrb*hrb + h0b*h0b));
    float f0r =  hra*inva, f0i = -h0a*inva;
    float f1r =  hrb*invb, f1i = -h0b*invb;
    g_FRF[b*64+t] = make_float4(f0r, f0i, f1r, f1i);
    float cr = f0r*f1r + f0i*f1i;
    float ci = f0i*f1r - f0r*f1i;
    __shared__ float s[6*64];
    s[0*64+t]=f0r; s[1*64+t]=f0i; s[2*64+t]=f1r; s[3*64+t]=f1i; s[4*64+t]=cr; s[5*64+t]=ci;
    __syncthreads();
    for (int off=32; off>=1; off>>=1){
        if (t < off){
            #pragma unroll
            for (int i=0;i<6;i++) s[i*64+t] += s[i*64+t+off];
        }
        __syncthreads();
    }
    if (t==0){
        g_colsum[b] = make_float4(s[0], s[64], s[128], s[192]);
        g_cross[b]  = make_float2(s[256], s[320]);
    }
}

// ---------------- K2: H_equ (normalized) + MLP input (smem reduction, R12-proven) ----------------
__global__ void k2_hequ(const float* __restrict__ H){
    __shared__ float4 sfrf[64];
    __shared__ float4 scs;
    __shared__ float sred[8*288];
    __shared__ float ssum[64];
    int b2 = blockIdx.x >> 2;
    int g  = blockIdx.x & 3;
    int tid = threadIdx.x;
    if (tid < 64) sfrf[tid] = g_FRF[b2*64 + tid];
    if (tid == 64) scs = g_colsum[b2];
    __syncthreads();
    int w = tid >> 5, l = tid & 31;
    int p = (g*8 + w)*4096 + b2;
    const float* r0 = H + (size_t)(2*p)*128;
    const float* r1 = r0 + 128;
    float a00r=0,a00i=0,a01r=0,a01i=0,a10r=0,a10i=0,a11r=0,a11i=0;
    #pragma unroll
    for (int k=0;k<2;k++){
        int tt = l + k*32;
        float4 f = sfrf[tt];
        float x0 = r0[tt], x1 = r1[tt];
        a00r += x0*f.x; a00i += x0*f.y; a01r += x0*f.z; a01i += x0*f.w;
        a10r += x1*f.x; a10i += x1*f.y; a11r += x1*f.z; a11i += x1*f.w;
    }
    float* dst = &sred[w*288 + l*9];
    dst[0]=a00r; dst[1]=a00i; dst[2]=a01r; dst[3]=a01i;
    dst[4]=a10r; dst[5]=a10i; dst[6]=a11r; dst[7]=a11i;
    __syncthreads();
    if (tid < 64){
        int w2 = tid >> 3, v = tid & 7;
        float s = 0.f;
        #pragma unroll
        for (int ll = 0; ll < 32; ll++) s += sred[w2*288 + ll*9 + v];
        ssum[tid] = s;
    }
    __syncthreads();
    if (tid < 8){
        int p2 = (g*8 + tid)*4096 + b2;
        const float* q0 = H + (size_t)(2*p2)*128;
        float h00 = q0[0], h01 = q0[128];
        float b00r=ssum[tid*8+0], b00i=ssum[tid*8+1], b01r=ssum[tid*8+2], b01i=ssum[tid*8+3];
        float b10r=ssum[tid*8+4], b10i=ssum[tid*8+5], b11r=ssum[tid*8+6], b11i=ssum[tid*8+7];
        float4 cs = scs;
        float m00r = b00r - h00*cs.y, m00i = b00i + h00*cs.x;
        float m01r = b01r - h00*cs.w, m01i = b01i + h00*cs.z;
        float m10r = b10r - h01*cs.y, m10i = b10i + h01*cs.x;
        float m11r = b11r - h01*cs.w, m11i = b11i + h01*cs.z;
        float pw = m00r*m00r+m00i*m00i+m01r*m01r+m01i*m01i
                 + m10r*m10r+m10i*m10i+m11r*m11r+m11i*m11i;
        float inv = 1.0f/sqrtf(pw);
        m00r*=inv; m00i*=inv; m01r*=inv; m01i*=inv;
        m10r*=inv; m10i*=inv; m11r*=inv; m11i*=inv;
        g_Hc[2*p2]   = make_float4(m00r,m00i,m01r,m01i);
        g_Hc[2*p2+1] = make_float4(m10r,m10i,m11r,m11i);
        float* xo = g_xin + (size_t)p2*8;
        xo[0]=m00r; xo[1]=m01r; xo[2]=m10r; xo[3]=m11r;
        xo[4]=m00i; xo[5]=m01i; xo[6]=m10i; xo[7]=m11i;
    }
}

// ---------------- weight split (+ bisection state init) ----------------
__global__ void k_wsplit(const float* __restrict__ W1, const float* __restrict__ W2){
    if (blockIdx.x == 0 && threadIdx.x == 0){
        g_ticket = 0u;
        for (int i = 0; i < 5; i++) g_dec5[i] = 0;
    }
    int idx = blockIdx.x*256 + threadIdx.x;     // 0..131071
    int layer = idx >> 16;
    int e = idx & 65535;
    int n = e & 255, k = e >> 8;
    float v = (layer ? W2 : W1)[k*256 + n];
    __nv_bfloat16 h = __float2bfloat16(v);
    __nv_bfloat16 l = __float2bfloat16(v - __bfloat162float(h));
    int pos = (k >> 4)*4096 + n*16 + (k & 15);
    if (layer){ g_W2hi[pos] = h; g_W2lo[pos] = l; }
    else      { g_W1hi[pos] = h; g_W1lo[pos] = l; }
}

// ---------------- K3: mma.sync bf16x3 MLP (256 thr, 3-buf swizzled, 1 pair-bar/chunk) ----------------
#define SA_HI   0          // 128 rows x 264 halves (stride 528B) = 67584
#define SA_LO   67584
#define SW_OFF  135168     // 3 buf x (hi 8192 + lo 8192) = 49152  (same region as before)
#define SW0_OFF 184320
#define SW3_OFF 192512
#define SB0_OFF 200704
#define SB1_OFF 201728
#define SB2_OFF 202752
#define SB3_OFF 203776
#define K3_SMEM 203904

// 32B/row swizzled buffer: unit h8 of row n at n*32 + ((h8 ^ ((n>>2)&1))*16)
__device__ __forceinline__ void issue_wp3(char* sm, int gch, int n){
    int layer = gch >> 4, c = gch & 15, buf = gch % 3;
    const __nv_bfloat16* gh = layer ? g_W2hi : g_W1hi;
    const __nv_bfloat16* gl = layer ? g_W2lo : g_W1lo;
    int sw = ((n >> 2) & 1)*16;
    char* dhi = sm + SW_OFF + buf*16384 + n*32;
    char* dlo = dhi + 8192;
    const __nv_bfloat16* srch = gh + c*4096 + n*16;
    const __nv_bfloat16* srcl = gl + c*4096 + n*16;
    __pipeline_memcpy_async(dhi + sw,        srch,     16);
    __pipeline_memcpy_async(dhi + (16^sw),   srch + 8, 16);
    __pipeline_memcpy_async(dlo + sw,        srcl,     16);
    __pipeline_memcpy_async(dlo + (16^sw),   srcl + 8, 16);
    __pipeline_commit();
}

__global__ void __launch_bounds__(256, 1) k3_mma(
        const float* __restrict__ W0, const float* __restrict__ b0v,
        const float* __restrict__ b1v, const float* __restrict__ b2v,
        const float* __restrict__ W3, const float* __restrict__ b3v){
    extern __shared__ char sm[];
    uint32_t sbase = smem_u32(sm);
    int tid  = threadIdx.x;
    int wid  = tid >> 5, lane = tid & 31;
    int wm   = wid >> 2;        // rowgroup 0..1 (64 rows)
    int wn   = wid & 3;         // ngroup  0..3 (64 cols)
    int prow = wn*64 + wm*32 + lane;   // this thread's B-row (pair region)
    int barid = 1 + wn;

    issue_wp3(sm, 0, prow);
    issue_wp3(sm, 1, prow);

    float* sW0 = (float*)(sm + SW0_OFF);
    float* sW3 = (float*)(sm + SW3_OFF);
    float* sB0 = (float*)(sm + SB0_OFF);
    float* sB1 = (float*)(sm + SB1_OFF);
    float* sB2 = (float*)(sm + SB2_OFF);
    float* sB3 = (float*)(sm + SB3_OFF);
    #pragma unroll
    for (int i = tid; i < 2048; i += 256){ sW0[i] = W0[i]; sW3[i] = W3[i]; }
    if (tid < 256){ sB0[tid] = b0v[tid]; sB1[tid] = b1v[tid]; sB2[tid] = b2v[tid]; }
    if (tid < 8) sB3[tid] = b3v[tid];

    // ---- layer0: 8 -> 256 FFMA, split, write SA ----
    int r = tid >> 1, h = tid & 1;
    int grow = blockIdx.x*128 + r;
    float xr[8];
    {
        float4 a = *(const float4*)(g_xin + (size_t)grow*8);
        float4 b = *(const float4*)(g_xin + (size_t)grow*8 + 4);
        xr[0]=a.x; xr[1]=a.y; xr[2]=a.z; xr[3]=a.w;
        xr[4]=b.x; xr[5]=b.y; xr[6]=b.z; xr[7]=b.w;
    }
    __syncthreads();
    {
        char* rowh = sm + SA_HI + r*528;
        char* rowl = sm + SA_LO + r*528;
        #pragma unroll 4
        for (int cc = 0; cc < 64; cc++){
            int c0 = h*128 + 2*cc;
            float e = sB0[c0], o = sB0[c0+1];
            #pragma unroll
            for (int i = 0; i < 8; i++){
                e += xr[i]*sW0[i*256 + c0];
                o += xr[i]*sW0[i*256 + c0 + 1];
            }
            e = fmaxf(e, 0.f); o = fmaxf(o, 0.f);
            uint32_t hi = pack_bf16x2(e, o);
            float eh = __uint_as_float(hi << 16);
            float oh = __uint_as_float(hi & 0xffff0000u);
            uint32_t lo = pack_bf16x2(e - eh, o - oh);
            *(uint32_t*)(rowh + c0*2) = hi;
            *(uint32_t*)(rowl + c0*2) = lo;
        }
    }
    __syncthreads();

    // ---- layers 1,2: mma over 32 global chunks; 3-buf, one pair-bar per chunk ----
    float acc[128];
    #pragma unroll
    for (int i = 0; i < 128; i++) acc[i] = 0.f;

    int arow   = wm*64 + (lane & 15);
    uint32_t aoff = (uint32_t)arow*528 + ((lane >> 4) & 1)*16;
    int nrow   = wn*64 + (lane & 7) + ((lane & 16) >> 1);
    uint32_t boff = (uint32_t)nrow*32 + (uint32_t)((((lane >> 3) & 1) ^ ((nrow >> 2) & 1))*16);

    #pragma unroll 1
    for (int gch = 0; gch < 32; gch++){
        if (gch < 31) __pipeline_wait_prior(1);
        else          __pipeline_wait_prior(0);
        PAIRBAR(barid);           // chunk gch visible; both warps past gch-1 -> buf (gch+2)%3 free
        if (gch + 2 < 32) issue_wp3(sm, gch + 2, prow);
        int buf = gch % 3;
        int c   = gch & 15;
        uint32_t wbh = sbase + SW_OFF + (uint32_t)buf*16384 + boff;
        uint32_t wbl = wbh + 8192;
        uint32_t bh[16], bl[16];
        #pragma unroll
        for (int ntp = 0; ntp < 4; ntp++){
            ldsm4(&bh[ntp*4], wbh + ntp*512);
            ldsm4(&bl[ntp*4], wbl + ntp*512);
        }
        uint32_t abase = sbase + aoff + (uint32_t)c*32;
        uint32_t ah[16], al[16];
        #pragma unroll
        for (int mf = 0; mf < 4; mf++){
            ldsm4(&ah[mf*4], abase + SA_HI + mf*8448);
            ldsm4(&al[mf*4], abase + SA_LO + mf*8448);
        }
        #pragma unroll
        for (int prod = 0; prod < 3; prod++){
            const uint32_t* A  = (prod == 1) ? al : ah;
            const uint32_t* Bf = (prod == 2) ? bl : bh;
            #pragma unroll
            for (int mf = 0; mf < 4; mf++){
                #pragma unroll
                for (int nt = 0; nt < 8; nt++){
                    mma_bf16(&acc[(mf*8 + nt)*4], &A[mf*4],
                             &Bf[(nt >> 1)*4 + (nt & 1)*2]);
                }
            }
        }
        if (c == 15){
            __syncthreads();   // all warps done reading SA for this layer
            const float* sb = (gch >> 4) ? sB2 : sB1;
            int erow = wm*64 + (lane >> 2);
            int ecol = wn*64 + (lane & 3)*2;
            #pragma unroll
            for (int mf = 0; mf < 4; mf++){
                #pragma unroll
                for (int nt = 0; nt < 8; nt++){
                    float* C = &acc[(mf*8 + nt)*4];
                    int col = ecol + nt*8;
                    float bv0 = sb[col], bv1 = sb[col+1];
                    #pragma unroll
                    for (int half = 0; half < 2; half++){
                        int row = erow + mf*16 + half*8;
                        float v0 = fmaxf(C[half*2]   + bv0, 0.f);
                        float v1 = fmaxf(C[half*2+1] + bv1, 0.f);
                        uint32_t hi = pack_bf16x2(v0, v1);
                        float eh = __uint_as_float(hi << 16);
                        float oh = __uint_as_float(hi & 0xffff0000u);
                        uint32_t lo = pack_bf16x2(v0 - eh, v1 - oh);
                        *(uint32_t*)(sm + SA_HI + row*528 + col*2) = hi;
                        *(uint32_t*)(sm + SA_LO + row*528 + col*2) = lo;
                        C[half*2] = 0.f; C[half*2+1] = 0.f;
                    }
                }
            }
            __syncthreads();   // epilogue SA writes complete before next layer's A-ldsm
        }
    }

    // ---- layer3: 256 -> 8 FFMA from SA ----
    {
        float a3[8];
        #pragma unroll
        for (int cc = 0; cc < 8; cc++) a3[cc] = 0.f;
        char* rowh = sm + SA_HI + r*528;
        char* rowl = sm + SA_LO + r*528;
        #pragma unroll 4
        for (int kk = 0; kk < 64; kk++){
            int k = h*128 + 2*kk;
            uint32_t wh = *(uint32_t*)(rowh + k*2);
            uint32_t wl = *(uint32_t*)(rowl + k*2);
            float v0 = __uint_as_float(wh << 16)          + __uint_as_float(wl << 16);
            float v1 = __uint_as_float(wh & 0xffff0000u)  + __uint_as_float(wl & 0xffff0000u);
            #pragma unroll
            for (int cc = 0; cc < 8; cc++){
                a3[cc] += v0*sW3[k*8 + cc] + v1*sW3[(k+1)*8 + cc];
            }
        }
        #pragma unroll
        for (int cc = 0; cc < 8; cc++)
            a3[cc] += __shfl_xor_sync(0xffffffffu, a3[cc], 1);
        if (h == 0){
            float* xo = g_xout + (size_t)grow*8;
            #pragma unroll
            for (int cc = 0; cc < 8; cc++) xo[cc] = a3[cc] + sB3[cc];
        }
    }
}

// ---------------- K4 + bisection(4 steps/barrier) + K5 fused (R8-proven) ----------------
__global__ void __launch_bounds__(256, 2) k_bis(){
    int tid = threadIdx.x;
    int bid = blockIdx.x;
    int gid = bid*256 + tid;        // 0..65535
    int lane = tid & 31, wid = tid >> 5;

    float A0[2],A1[2],A2[2],Cc0[2],Cc1[2],Cc2[2],Cc3[2];
    float Bar[2],Bai[2],Bbr[2],Bbi[2],Bcr[2],Bci[2],Bdr[2],Bdi[2];
    float uwr0[2],uwi0[2],uwr1[2],uwi1[2];
    float hc[2][8];

    #pragma unroll
    for (int q = 0; q < 2; q++){
        int p = gid + q*65536;
        float4 hc0 = g_Hc[2*p], hc1 = g_Hc[2*p+1];
        hc[q][0]=hc0.x; hc[q][1]=hc0.y; hc[q][2]=hc0.z; hc[q][3]=hc0.w;
        hc[q][4]=hc1.x; hc[q][5]=hc1.y; hc[q][6]=hc1.z; hc[q][7]=hc1.w;
        const float* x = g_xout + (size_t)p*8;
        float x0=x[0],x1=x[1],x2=x[2],x3=x[3],x4=x[4],x5=x[5],x6=x[6],x7=x[7];
        cf U0{x0,x2}, U1{x1,x3}, Wm0{x4,x6}, Wm1{x5,x7};
        float au0 = x0*x0 + x2*x2, au1 = x1*x1 + x3*x3;
        cf c0{Wm0.r*au0, Wm0.i*au0}, c1{Wm1.r*au1, Wm1.i*au1};
        cf h00{hc0.x,hc0.y}, h01{hc0.z,hc0.w}, h10{hc1.x,hc1.y}, h11{hc1.z,hc1.w};
        float n00 = cabs2(h00), n01 = cabs2(h01), n10 = cabs2(h10), n11 = cabs2(h11);
        cf Ba{c0.r*n00 + c1.r*n10, c0.i*n00 + c1.i*n10};
        cf Bd{c0.r*n01 + c1.r*n11, c0.i*n01 + c1.i*n11};
        cf Bb = cadd(cmul(c0, cmul(cconj(h00), h01)), cmul(c1, cmul(cconj(h10), h11)));
        cf Bc = cadd(cmul(c0, cmul(cconj(h01), h00)), cmul(c1, cmul(cconj(h11), h10)));
        cf uw0 = cmul(U0, Wm0), uw1 = cmul(U1, Wm1);
        cf g00 = cconj(h00), g01 = cconj(h01), g10 = cconj(h10), g11 = cconj(h11);
        cf p00 = csub(cmul(Bd,g00), cmul(Bb,g01));
        cf p01 = csub(cmul(Ba,g01), cmul(Bc,g00));
        cf p10 = csub(cmul(Bd,g10), cmul(Bb,g11));
        cf p11 = csub(cmul(Ba,g11), cmul(Bc,g10));
        float u0 = cabs2(uw0), u1 = cabs2(uw1);
        A0[q] = u0*(cabs2(p00)+cabs2(p01)) + u1*(cabs2(p10)+cabs2(p11));
        A1[q] = 2.f*( u0*(p00.r*g00.r + p00.i*g00.i + p01.r*g01.r + p01.i*g01.i)
                    + u1*(p10.r*g10.r + p10.i*g10.i + p11.r*g11.r + p11.i*g11.i) );
        A2[q] = u0*(cabs2(g00)+cabs2(g01)) + u1*(cabs2(g10)+cabs2(g11));
        cf T = cadd(Ba, Bd);
        cf D = csub(cmul(Ba,Bd), cmul(Bb,Bc));
        Cc0[q] = cabs2(D);
        Cc1[q] = 2.f*(T.r*D.r + T.i*D.i);
        Cc2[q] = T.r*T.r + T.i*T.i + 2.f*D.r;
        Cc3[q] = 2.f*T.r;
        Bar[q]=Ba.r; Bai[q]=Ba.i; Bbr[q]=Bb.r; Bbi[q]=Bb.i;
        Bcr[q]=Bc.r; Bci[q]=Bc.i; Bdr[q]=Bd.r; Bdi[q]=Bd.i;
        uwr0[q]=uw0.r; uwi0[q]=uw0.i; uwr1[q]=uw1.r; uwi1[q]=uw1.i;
    }

    __shared__ float swarp[8][16];
    __shared__ float spart[16][16];
    __shared__ float ssum[16];
    __shared__ int   slast;
    float lo = 0.f, hi = 10.f, mu = 5.f;

    #pragma unroll 1
    for (int round = 0; round < 5; round++){
        float L[16], Hh[16], m[16];
        L[1] = lo; Hh[1] = hi;
        #pragma unroll
        for (int i = 1; i < 8; i++){
            m[i] = 0.5f*(L[i] + Hh[i]);
            L[2*i] = L[i];  Hh[2*i] = m[i];
            L[2*i+1] = m[i]; Hh[2*i+1] = Hh[i];
        }
        #pragma unroll
        for (int i = 8; i < 16; i++) m[i] = 0.5f*(L[i] + Hh[i]);

        float v[15];
        #pragma unroll
        for (int node = 1; node <= 15; node++){
            float s = 2.0f*m[node];
            float a = 0.f;
            #pragma unroll
            for (int q = 0; q < 2; q++){
                float num = A0[q] + s*(A1[q] + s*A2[q]);
                float den = Cc0[q] + s*(Cc1[q] + s*(Cc2[q] + s*(Cc3[q] + s)));
                a += num/den;
            }
            v[node-1] = a;
        }
        #pragma unroll
        for (int j = 0; j < 15; j++){
            #pragma unroll
            for (int off = 16; off; off >>= 1)
                v[j] += __shfl_down_sync(0xffffffffu, v[j], off);
            if (lane == 0) swarp[wid][j] = v[j];
        }
        __syncthreads();
        if (tid < 15){
            float s = 0.f;
            #pragma unroll
            for (int w = 0; w < 8; w++) s += swarp[w][tid];
            g_part15[bid][tid] = s;
        }
        __threadfence();
        __syncthreads();
        if (tid == 0){
            unsigned old = atomicAdd(&g_ticket, 1u);
            slast = (old == (unsigned)(256*(round+1) - 1)) ? 1 : 0;
        }
        __syncthreads();
        if (slast){
            int j = tid & 15, chunk = tid >> 4;
            float sacc = 0.f;
            if (j < 15){
                volatile float* gp = &g_part15[0][0];
                int base = chunk*16;
                #pragma unroll
                for (int i = 0; i < 16; i++) sacc += gp[(base + i)*16 + j];
            }
            spart[chunk][j] = sacc;
            __syncthreads();
            if (tid < 15){
                float s = 0.f;
                #pragma unroll
                for (int cc = 0; cc < 16; cc++) s += spart[cc][tid];
                g_sum15[round][tid] = s;
            }
            __threadfence();
            __syncthreads();
            if (tid == 0){ g_dec5[round] = 1; __threadfence(); }
        }
        if (tid == 0){
            volatile int* dp = (volatile int*)&g_dec5[round];
            int d;
            do { d = *dp; } while (d == 0);
            __threadfence();
            volatile float* gs = &g_sum15[round][0];
            #pragma unroll
            for (int j = 0; j < 15; j++) ssum[j] = gs[j];
        }
        __syncthreads();
        float Lc = lo, Hc = hi;
        int node = 1;
        #pragma unroll
        for (int st = 0; st < 4; st++){
            float mm = 0.5f*(Lc + Hc);
            float S = ssum[node-1];
            mu = mm;
            if (S > 1.0f){ Lc = mm; node = 2*node + 1; }
            else         { Hc = mm; node = 2*node; }
        }
        lo = Lc; hi = Hc;
        __syncthreads();
    }

    // epilogue: final V + per-item power
    float s = 2.0f*mu;
    #pragma unroll
    for (int q = 0; q < 2; q++){
        int p = gid + q*65536;
        cf a{Bar[q] + s, Bai[q]}, b{Bbr[q], Bbi[q]}, c{Bcr[q], Bci[q]}, d{Bdr[q] + s, Bdi[q]};
        cf det = csub(cmul(a,d), cmul(b,c));
        float id = 1.0f/cabs2(det);
        cf idet{det.r*id, -det.i*id};
        cf g00{hc[q][0],-hc[q][1]}, g01{hc[q][2],-hc[q][3]};
        cf g10{hc[q][4],-hc[q][5]}, g11{hc[q][6],-hc[q][7]};
        cf y00 = cmul(csub(cmul(d,g00), cmul(b,g01)), idet);
        cf y01 = cmul(csub(cmul(a,g01), cmul(c,g00)), idet);
        cf y10 = cmul(csub(cmul(d,g10), cmul(b,g11)), idet);
        cf y11 = cmul(csub(cmul(a,g11), cmul(c,g10)), idet);
        cf uw0{uwr0[q],uwi0[q]}, uw1{uwr1[q],uwi1[q]};
        cf V00 = cmul(uw0,y00);
        cf V01 = cmul(uw1,y10);
        cf V10 = cmul(uw0,y01);
        cf V11 = cmul(uw1,y11);
        g_V[2*p]   = make_float4(V00.r,V00.i,V01.r,V01.i);
        g_V[2*p+1] = make_float4(V10.r,V10.i,V11.r,V11.i);
        float2 cr = g_cross[p & 4095];
        cf crs{cr.x, cr.y};
        cf t0 = cmul(crs, cmul(V00, cconj(V10)));
        cf t1 = cmul(crs, cmul(V01, cconj(V11)));
        g_Pw[p] = cabs2(V00)+cabs2(V10)+2.f*t0.r + cabs2(V01)+cabs2(V11)+2.f*t1.r;
    }
}

// ---------------- K6: output ----------------
__global__ void k6_out(float* __restrict__ out){
    int q = blockIdx.x*8 + (threadIdx.x >> 5);
    int l = threadIdx.x & 31;
    int n2 = q >> 12;
    int b3 = q & 4095;
    float sc = 1.41421356237f / sqrtf(g_Pw[b3*32 + n2]);
    float4 v0 = g_V[2*q], v1 = g_V[2*q+1];
    cf V00{v0.x,v0.y}, V01{v0.z,v0.w}, V10{v1.x,v1.y}, V11{v1.z,v1.w};
    const float4* frf = g_FRF + b3*64;
    float* baseR = out + (size_t)b3*8192 + n2*128;
    float* baseI = baseR + 4096;
    float4 fa = frf[2*l], fb = frf[2*l+1];
    cf fa0{fa.x,fa.y}, fa1{fa.z,fa.w}, fb0{fb.x,fb.y}, fb1{fb.z,fb.w};
    cf oa0 = cadd(cmul(fa0,V00), cmul(fa1,V10));
    cf oa1 = cadd(cmul(fa0,V01), cmul(fa1,V11));
    cf ob0 = cadd(cmul(fb0,V00), cmul(fb1,V10));
    cf ob1 = cadd(cmul(fb0,V01), cmul(fb1,V11));
    ((float4*)baseR)[l] = make_float4(sc*oa0.r, sc*oa1.r, sc*ob0.r, sc*ob1.r);
    ((float4*)baseI)[l] = make_float4(sc*oa0.i, sc*oa1.i, sc*ob0.i, sc*ob1.i);
}

// ---------------- launch ----------------
extern "C" void kernel_launch(void* const* d_in, const int* in_sizes, int n_in,
                              void* d_out, int out_size){
    const float* H  = (const float*)d_in[0];
    const float* W0 = (const float*)d_in[1]; const float* b0 = (const float*)d_in[2];
    const float* W1 = (const float*)d_in[3]; const float* b1 = (const float*)d_in[4];
    const float* W2 = (const float*)d_in[5]; const float* b2 = (const float*)d_in[6];
    const float* W3 = (const float*)d_in[7]; const float* b3 = (const float*)d_in[8];
    cudaFuncSetAttribute(k3_mma, cudaFuncAttributeMaxDynamicSharedMemorySize, K3_SMEM);

    k_wsplit<<<512,256>>>(W1, W2);
    k1_frf<<<BATCHN,64>>>(H);
    k2_hequ<<<16384,256>>>(H);
    k3_mma<<<1024,256,K3_SMEM>>>(W0, b0, b1, b2, W3, b3);
    k_bis<<<256,256>>>();
    k6_out<<<16384,256>>>((float*)d_out);
}